// round 13
// baseline (speedup 1.0000x reference)
#include <cuda_runtime.h>
#include <cstdint>

// Problem constants
#define BB 4
#define SS 2048
#define DD 512
#define HH 8
#define HD 64
#define MROWS (BB*SS)   // 8192

// Scratch (static device arrays -- allocation-free per harness rules)
__device__ float g_gate[BB*SS*DD];       // [b,s,d]
__device__ float g_q[BB*HH*SS*HD];       // [b,h,s,d]
__device__ float g_k[BB*HH*SS*HD];
__device__ float g_v[BB*HH*SS*HD];
__device__ float g_o[BB*SS*DD];          // [b,s,d]
__device__ float g_ng[BB*SS*DD];         // layernorm(o) * gate

__device__ __forceinline__ float silu_f(float x) {
    return __fdividef(x, 1.0f + __expf(-x));
}
__device__ __forceinline__ uint32_t f2tf(float x) {
    uint32_t r; asm("cvt.rna.tf32.f32 %0, %1;" : "=r"(r) : "f"(x)); return r;
}
// D = A(16x8,row) * B(8x8,col) + D, tf32 in, f32 accum
__device__ __forceinline__ void mma_tf32(float* c, const uint32_t* a, const uint32_t* b) {
    asm volatile(
        "mma.sync.aligned.m16n8k8.row.col.f32.tf32.tf32.f32 "
        "{%0,%1,%2,%3}, {%4,%5,%6,%7}, {%8,%9}, {%0,%1,%2,%3};"
        : "+f"(c[0]), "+f"(c[1]), "+f"(c[2]), "+f"(c[3])
        : "r"(a[0]), "r"(a[1]), "r"(a[2]), "r"(a[3]), "r"(b[0]), "r"(b[1]));
}

// ---------------------------------------------------------------------------
// tf32 mma.sync GEMM: C[M,N] = A[M,512] @ W[N,512]^T (+bias, +epilogue)
// CTA: 128x128 tile, 256 threads = 8 warps (2 M x 4 N), warp = 64x32.
// FRAGMENT-MAJOR smem: each lane's m16n8k8 A-fragment (4 words) and
// B-fragment (2 words) are stored contiguously -> af = 1 LDS.128, bf =
// 1 LDS.64 (was 4 / 2 LDS.32). All smem traffic lane-contiguous =>
// conflict-free. Staging gathers fragments with scalar LDG.32 (overlapped
// under the MMA loop via register prefetch, R11 structure).
//   A layout: word(r,k) at ((R*4+Kb)*32 + g*4 + t)*4 + half + 2*khalf
//             R=r>>4, half=(r>>3)&1, g=r&7, Kb=k>>3, khalf=(k>>2)&1, t=k&3
//   B layout: word(n,k) at ((N8*4+Kb)*32 + g*4 + t)*2 + khalf
//             N8=n>>3, g=n&7
// MODE 0: A = x,    epilogue = silu(.)+scatter to gate/q/k/v  (N = 2048)
// MODE 1: A = g_ng, epilogue = +b2 -> out                     (N = 512)
// ---------------------------------------------------------------------------
template<int MODE>
__global__ void __launch_bounds__(256) tc_gemm(
    const float* __restrict__ A_in,
    const float* __restrict__ W,
    const float* __restrict__ bias,
    float* __restrict__ out)
{
    __shared__ uint32_t Asf[4096];   // 8 R-blocks x 4 K-blocks x 32 lanes x 4
    __shared__ uint32_t Bsf[4096];   // 16 N8-blocks x 4 K-blocks x 32 lanes x 2

    const float* A = (MODE == 0) ? A_in : g_ng;
    const int tid  = threadIdx.x;
    const int wid  = tid >> 5;
    const int lane = tid & 31;
    const int g    = lane >> 2;
    const int t    = lane & 3;
    const int row0 = blockIdx.y * 128;
    const int col0 = blockIdx.x * 128;
    const int wm   = (wid >> 2) * 64;
    const int wn   = (wid & 3) * 32;
    const int Rb   = (wid >> 2) * 4;   // MMA A-block row base (R = Rb+mt)
    const int N8b  = (wid & 3) * 4;    // MMA B-block base (N8 = N8b+nt)

    // Staging source pointers: warp `wid` stages A rows [wid*16, wid*16+16)
    // and B rows [wid*16, wid*16+16) (as two N8 blocks).
    const float* a0p = A + (size_t)(row0 + wid * 16 + g) * 512 + t;
    const float* a1p = a0p + 8 * 512;
    const float* b0p = W + (size_t)(col0 + wid * 16 + g) * 512 + t;
    const float* b1p = b0p + 8 * 512;

    float acc[4][4][4];
    #pragma unroll
    for (int i = 0; i < 4; i++)
        #pragma unroll
        for (int j = 0; j < 4; j++)
            #pragma unroll
            for (int q = 0; q < 4; q++) acc[i][j][q] = 0.0f;

    // prefetch K-block 0 (fragment gathers)
    float4 pa[4];
    float2 pb[8];
    #pragma unroll
    for (int i = 0; i < 4; i++) {
        const int c = i * 8;
        pa[i] = make_float4(a0p[c], a1p[c], a0p[c + 4], a1p[c + 4]);
    }
    #pragma unroll
    for (int i = 0; i < 8; i++) {
        const float* bp = (i < 4) ? b0p : b1p;
        const int c = (i & 3) * 8;
        pb[i] = make_float2(bp[c], bp[c + 4]);
    }

    for (int kb = 0; kb < 16; kb++) {
        // store prefetched fragments (conflict-free STS.128 / STS.64)
        #pragma unroll
        for (int i = 0; i < 4; i++)
            *(uint4*)&Asf[((wid * 4 + i) * 32 + lane) * 4] =
                make_uint4(f2tf(pa[i].x), f2tf(pa[i].y), f2tf(pa[i].z), f2tf(pa[i].w));
        #pragma unroll
        for (int i = 0; i < 8; i++)
            *(uint2*)&Bsf[((wid * 8 + i) * 32 + lane) * 2] =
                make_uint2(f2tf(pb[i].x), f2tf(pb[i].y));
        __syncthreads();

        // prefetch next block; LDG latency hides under the MMA loop
        if (kb < 15) {
            const int k0 = (kb + 1) * 32;
            #pragma unroll
            for (int i = 0; i < 4; i++) {
                const int c = k0 + i * 8;
                pa[i] = make_float4(a0p[c], a1p[c], a0p[c + 4], a1p[c + 4]);
            }
            #pragma unroll
            for (int i = 0; i < 8; i++) {
                const float* bp = (i < 4) ? b0p : b1p;
                const int c = k0 + (i & 3) * 8;
                pb[i] = make_float2(bp[c], bp[c + 4]);
            }
        }

        // MMA: per k8, 4 LDS.128 + 4 LDS.64 feed 16 MMAs
        #pragma unroll
        for (int k8 = 0; k8 < 4; k8++) {
            uint32_t af[4][4];
            #pragma unroll
            for (int mt = 0; mt < 4; mt++)
                *(uint4*)af[mt] =
                    *(const uint4*)&Asf[(((Rb + mt) * 4 + k8) * 32 + lane) * 4];
            uint32_t bf[4][2];
            #pragma unroll
            for (int nt = 0; nt < 4; nt++)
                *(uint2*)bf[nt] =
                    *(const uint2*)&Bsf[(((N8b + nt) * 4 + k8) * 32 + lane) * 2];
            #pragma unroll
            for (int mt = 0; mt < 4; mt++)
                #pragma unroll
                for (int nt = 0; nt < 4; nt++)
                    mma_tf32(acc[mt][nt], af[mt], bf[nt]);
        }
        __syncthreads();
    }

    #pragma unroll
    for (int mt = 0; mt < 4; mt++) {
        #pragma unroll
        for (int half = 0; half < 2; half++) {
            const int r = row0 + wm + mt * 16 + g + half * 8;
            const int b = r >> 11;
            const int s = r & 2047;
            #pragma unroll
            for (int nt = 0; nt < 4; nt++) {
                const int j = col0 + wn + nt * 8 + 2 * t;
                float2 v;
                v.x = acc[mt][nt][half * 2 + 0] + __ldg(&bias[j]);
                v.y = acc[mt][nt][half * 2 + 1] + __ldg(&bias[j + 1]);
                if (MODE == 0) {
                    v.x = silu_f(v.x);
                    v.y = silu_f(v.y);
                    const int c   = j >> 9;
                    const int rem = j & 511;
                    if (c == 0) {
                        *(float2*)&g_gate[(size_t)r * 512 + rem] = v;
                    } else {
                        const int head = rem >> 6;
                        const int d    = rem & 63;
                        float* dst = (c == 1) ? g_q : ((c == 2) ? g_k : g_v);
                        *(float2*)&dst[((size_t)(b * 8 + head) * 2048 + s) * 64 + d] = v;
                    }
                } else {
                    *(float2*)&out[(size_t)r * 512 + j] = v;
                }
            }
        }
    }
}

// ---------------------------------------------------------------------------
// Causal HSTU attention on tf32 mma.sync (R11 code, known-good 406us config).
// Block: 256 thr = 8 warps (4 M x 2 N), 128-query tile per block. Register
// prefetch of next K/V tile overlaps LDG latency with the MMA loops.
// ---------------------------------------------------------------------------
#define AQST 68   // smem word stride; 68 mod 32 = 4 -> conflict-free frags

__global__ void __launch_bounds__(256) attn_mma_kernel() {
    extern __shared__ uint32_t smw[];
    uint32_t* Qs = smw;                  // [128][AQST] tf32 [query][dim]
    uint32_t* Ks = smw + 128 * AQST;     // [64][AQST]  tf32 [key][dim]
    uint32_t* Vt = smw + 192 * AQST;     // [64][AQST]  tf32 [dim][key]
    uint32_t* St = smw + 256 * AQST;     // [128][AQST] tf32 [query][key]

    const int tid  = threadIdx.x;
    const int wid  = tid >> 5;
    const int lane = tid & 31;
    const int g    = lane >> 2;
    const int t    = lane & 3;
    const int qt   = blockIdx.x;         // 0..15 (128-query tiles)
    const int bh   = blockIdx.y;
    const int b    = bh >> 3;
    const int h    = bh & 7;
    const size_t base = (size_t)bh * SS * HD;
    const float* qp = g_q + base;
    const float* kp = g_k + base;
    const float* vp = g_v + base;
    const int s0 = qt * 128;
    const int wm = (wid >> 1) * 32;      // query offset: 0,32,64,96
    const int wn = (wid & 1) * 32;       // key/dim offset: 0,32

    // Stage Q (128 x 64, tf32)
    #pragma unroll
    for (int l = 0; l < 8; l++) {
        const int idx = tid + l * 256;
        const int r   = idx >> 4;
        const int c4  = (idx & 15) << 2;
        float4 qv = *(const float4*)&qp[(size_t)(s0 + r) * 64 + c4];
        *(uint4*)&Qs[r * AQST + c4] =
            make_uint4(f2tf(qv.x), f2tf(qv.y), f2tf(qv.z), f2tf(qv.w));
    }

    float oacc[2][4][4];
    #pragma unroll
    for (int m = 0; m < 2; m++)
        #pragma unroll
        for (int i = 0; i < 4; i++)
            #pragma unroll
            for (int j = 0; j < 4; j++) oacc[m][i][j] = 0.0f;

    const int last = 2 * qt + 1;

    // prefetch K/V tile 0
    float4 pk[4], pv[4];
    #pragma unroll
    for (int l = 0; l < 4; l++) {
        const int idx = tid + l * 256;
        const int r   = idx >> 4;
        const int c4  = (idx & 15) << 2;
        pk[l] = *(const float4*)&kp[(size_t)r * 64 + c4];
        pv[l] = *(const float4*)&vp[(size_t)r * 64 + c4];
    }

    for (int kt = 0; kt <= last; kt++) {
        const int t0 = kt * 64;
        __syncthreads();   // prev-iter Ks/Vt/St reads done (and Qs staged, kt=0)

        // store prefetched K ([key][dim]) and V transposed ([dim][key])
        #pragma unroll
        for (int l = 0; l < 4; l++) {
            const int idx = tid + l * 256;
            const int r   = idx >> 4;
            const int c4  = (idx & 15) << 2;
            *(uint4*)&Ks[r * AQST + c4] =
                make_uint4(f2tf(pk[l].x), f2tf(pk[l].y), f2tf(pk[l].z), f2tf(pk[l].w));
            Vt[(c4 + 0) * AQST + r] = f2tf(pv[l].x);
            Vt[(c4 + 1) * AQST + r] = f2tf(pv[l].y);
            Vt[(c4 + 2) * AQST + r] = f2tf(pv[l].z);
            Vt[(c4 + 3) * AQST + r] = f2tf(pv[l].w);
        }
        __syncthreads();

        // prefetch next K/V tile; latency hides under the MMA loops
        if (kt < last) {
            const int tn = (kt + 1) * 64;
            #pragma unroll
            for (int l = 0; l < 4; l++) {
                const int idx = tid + l * 256;
                const int r   = idx >> 4;
                const int c4  = (idx & 15) << 2;
                pk[l] = *(const float4*)&kp[(size_t)(tn + r) * 64 + c4];
                pv[l] = *(const float4*)&vp[(size_t)(tn + r) * 64 + c4];
            }
        }

        // ---- GEMM 1: scores = Q @ K^T (per warp: M=32 queries, N=32 keys)
        float sacc[2][4][4];
        #pragma unroll
        for (int m = 0; m < 2; m++)
            #pragma unroll
            for (int i = 0; i < 4; i++)
                #pragma unroll
                for (int j = 0; j < 4; j++) sacc[m][i][j] = 0.0f;

        #pragma unroll
        for (int k8 = 0; k8 < 8; k8++) {
            const int kk = k8 * 8;
            uint32_t af[2][4];
            #pragma unroll
            for (int mt = 0; mt < 2; mt++) {
                const int mr = wm + mt * 16 + g;
                af[mt][0] = Qs[mr * AQST + kk + t];
                af[mt][1] = Qs[(mr + 8) * AQST + kk + t];
                af[mt][2] = Qs[mr * AQST + kk + t + 4];
                af[mt][3] = Qs[(mr + 8) * AQST + kk + t + 4];
            }
            uint32_t bf[4][2];
            #pragma unroll
            for (int nt = 0; nt < 4; nt++) {
                const int nr = wn + nt * 8 + g;
                bf[nt][0] = Ks[nr * AQST + kk + t];
                bf[nt][1] = Ks[nr * AQST + kk + t + 4];
            }
            #pragma unroll
            for (int mt = 0; mt < 2; mt++)
                #pragma unroll
                for (int nt = 0; nt < 4; nt++)
                    mma_tf32(sacc[mt][nt], af[mt], bf[nt]);
        }

        // silu + causal mask on fragments, re-round to tf32 into St
        const bool diag = (kt >= 2 * qt);
        #pragma unroll
        for (int mt = 0; mt < 2; mt++) {
            #pragma unroll
            for (int nt = 0; nt < 4; nt++) {
                const int klocal = wn + nt * 8 + 2 * t;
                const int key    = t0 + klocal;
                #pragma unroll
                for (int half = 0; half < 2; half++) {
                    const int qlocal = wm + mt * 16 + g + half * 8;
                    const int qrow   = s0 + qlocal;
                    float v0 = silu_f(sacc[mt][nt][half * 2 + 0] * 0.125f);
                    float v1 = silu_f(sacc[mt][nt][half * 2 + 1] * 0.125f);
                    if (diag) {
                        if (key     > qrow) v0 = 0.0f;
                        if (key + 1 > qrow) v1 = 0.0f;
                    }
                    *(uint2*)&St[qlocal * AQST + klocal] =
                        make_uint2(f2tf(v0), f2tf(v1));
                }
            }
        }
        __syncthreads();

        // ---- GEMM 2: O += St @ V  (A=St [query][key], B=Vt [dim][key])
        #pragma unroll
        for (int k8 = 0; k8 < 8; k8++) {
            const int kk = k8 * 8;
            uint32_t af[2][4];
            #pragma unroll
            for (int mt = 0; mt < 2; mt++) {
                const int mr = wm + mt * 16 + g;
                af[mt][0] = St[mr * AQST + kk + t];
                af[mt][1] = St[(mr + 8) * AQST + kk + t];
                af[mt][2] = St[mr * AQST + kk + t + 4];
                af[mt][3] = St[(mr + 8) * AQST + kk + t + 4];
            }
            uint32_t bf[4][2];
            #pragma unroll
            for (int nt = 0; nt < 4; nt++) {
                const int nr = wn + nt * 8 + g;
                bf[nt][0] = Vt[nr * AQST + kk + t];
                bf[nt][1] = Vt[nr * AQST + kk + t + 4];
            }
            #pragma unroll
            for (int mt = 0; mt < 2; mt++)
                #pragma unroll
                for (int nt = 0; nt < 4; nt++)
                    mma_tf32(oacc[mt][nt], af[mt], bf[nt]);
        }
    }

    // Write O in [b, s, h*64+dim] layout
    #pragma unroll
    for (int mt = 0; mt < 2; mt++) {
        #pragma unroll
        for (int nt = 0; nt < 4; nt++) {
            const int dim = wn + nt * 8 + 2 * t;
            #pragma unroll
            for (int half = 0; half < 2; half++) {
                const int srow = s0 + wm + mt * 16 + g + half * 8;
                float2 ov = make_float2(oacc[mt][nt][half * 2 + 0],
                                        oacc[mt][nt][half * 2 + 1]);
                *(float2*)&g_o[((size_t)(b * SS + srow)) * DD + h * 64 + dim] = ov;
            }
        }
    }
}

// ---------------------------------------------------------------------------
// LayerNorm(o) * gate  -> g_ng
// ---------------------------------------------------------------------------
__global__ void __launch_bounds__(128) ln_gate_kernel(
    const float* __restrict__ lng, const float* __restrict__ lnb)
{
    const int row = blockIdx.x;
    const int tid = threadIdx.x;
    const float* op = g_o + (size_t)row * DD;

    float4 x = *(const float4*)&op[tid * 4];
    float s = x.x + x.y + x.z + x.w;

    const int lane = tid & 31, wid = tid >> 5;
    __shared__ float r1[4], r2[4];

    #pragma unroll
    for (int off = 16; off; off >>= 1) s += __shfl_xor_sync(0xffffffffu, s, off);
    if (lane == 0) r1[wid] = s;
    __syncthreads();
    const float m = (r1[0] + r1[1] + r1[2] + r1[3]) * (1.0f / 512.0f);

    const float dx = x.x - m, dy = x.y - m, dz = x.z - m, dw = x.w - m;
    float sq = dx * dx + dy * dy + dz * dz + dw * dw;
    #pragma unroll
    for (int off = 16; off; off >>= 1) sq += __shfl_xor_sync(0xffffffffu, sq, off);
    if (lane == 0) r2[wid] = sq;
    __syncthreads();
    const float var = (r2[0] + r2[1] + r2[2] + r2[3]) * (1.0f / 512.0f);
    const float inv = rsqrtf(var + 1e-5f);

    float4 gv = *(const float4*)&lng[tid * 4];
    float4 bv = *(const float4*)&lnb[tid * 4];
    float4 gg = *(const float4*)&g_gate[(size_t)row * DD + tid * 4];
    float4 o;
    o.x = (dx * inv * gv.x + bv.x) * gg.x;
    o.y = (dy * inv * gv.y + bv.y) * gg.y;
    o.z = (dz * inv * gv.z + bv.z) * gg.z;
    o.w = (dw * inv * gv.w + bv.w) * gg.w;
    *(float4*)&g_ng[(size_t)row * DD + tid * 4] = o;
}

// ---------------------------------------------------------------------------
extern "C" void kernel_launch(void* const* d_in, const int* in_sizes, int n_in,
                              void* d_out, int out_size) {
    const float* x   = (const float*)d_in[0];
    const float* W1  = (const float*)d_in[1];
    const float* b1  = (const float*)d_in[2];
    const float* lng = (const float*)d_in[3];
    const float* lnb = (const float*)d_in[4];
    const float* W2  = (const float*)d_in[5];
    const float* b2  = (const float*)d_in[6];
    float* out = (float*)d_out;

    const int attn_smem = 384 * AQST * (int)sizeof(uint32_t);      // 104448 B
    cudaFuncSetAttribute(attn_mma_kernel,
                         cudaFuncAttributeMaxDynamicSharedMemorySize, attn_smem);

    // 1) h = silu(x @ W1^T + b1), scattered to gate/q/k/v   (tf32 mma.sync)
    tc_gemm<0><<<dim3(2048 / 128, MROWS / 128), 256>>>(x, W1, b1, out);

    // 2) causal silu-attention -> g_o [b,s,d]               (tf32 mma.sync)
    attn_mma_kernel<<<dim3(SS / 128, BB * HH), 256, attn_smem>>>();

    // 3) layernorm(o) * gate -> g_ng
    ln_gate_kernel<<<MROWS, 128>>>(lng, lnb);

    // 4) out = g_ng @ W2^T + b2                             (tf32 mma.sync)
    tc_gemm<1><<<dim3(512 / 128, MROWS / 128), 256>>>(nullptr, W2, b2, out);
}

// round 14
// speedup vs baseline: 1.3258x; 1.3258x over previous
#include <cuda_runtime.h>
#include <cstdint>

// Problem constants
#define BB 4
#define SS 2048
#define DD 512
#define HH 8
#define HD 64
#define MROWS (BB*SS)   // 8192

// Scratch (static device arrays -- allocation-free per harness rules)
__device__ float g_gate[BB*SS*DD];       // [b,s,d]
__device__ float g_q[BB*HH*SS*HD];       // [b,h,s,d]
__device__ float g_k[BB*HH*SS*HD];
__device__ float g_v[BB*HH*SS*HD];
__device__ float g_o[BB*SS*DD];          // [b,s,d]
__device__ float g_ng[BB*SS*DD];         // layernorm(o) * gate

__device__ __forceinline__ float silu_f(float x) {
    return __fdividef(x, 1.0f + __expf(-x));
}
__device__ __forceinline__ uint32_t f2tf(float x) {
    uint32_t r; asm("cvt.rna.tf32.f32 %0, %1;" : "=r"(r) : "f"(x)); return r;
}
__device__ __forceinline__ uint32_t smem_u32(const void* p) {
    uint32_t a;
    asm("{ .reg .u64 t; cvta.to.shared.u64 t, %1; cvt.u32.u64 %0, t; }"
        : "=r"(a) : "l"(p));
    return a;
}
// D = A(16x8,row) * B(8x8,col) + D, tf32 in, f32 accum
__device__ __forceinline__ void mma_tf32(float* c, const uint32_t* a, const uint32_t* b) {
    asm volatile(
        "mma.sync.aligned.m16n8k8.row.col.f32.tf32.tf32.f32 "
        "{%0,%1,%2,%3}, {%4,%5,%6,%7}, {%8,%9}, {%0,%1,%2,%3};"
        : "+f"(c[0]), "+f"(c[1]), "+f"(c[2]), "+f"(c[3])
        : "r"(a[0]), "r"(a[1]), "r"(a[2]), "r"(a[3]), "r"(b[0]), "r"(b[1]));
}
// ldmatrix: 4x (8 rows x 16B) tiles -> full tf32 m16n8k8 A fragment.
// Lane mapping (2 b16 = 1 tf32 word) matches the mma fragment exactly.
__device__ __forceinline__ void ldsm_x4(uint32_t* r, uint32_t addr) {
    asm volatile("ldmatrix.sync.aligned.m8n8.x4.shared.b16 {%0,%1,%2,%3}, [%4];"
                 : "=r"(r[0]), "=r"(r[1]), "=r"(r[2]), "=r"(r[3]) : "r"(addr));
}
// 2 tiles -> tf32 m16n8k8 B fragment (col-major B stored as [n][k]).
__device__ __forceinline__ void ldsm_x2(uint32_t* r, uint32_t addr) {
    asm volatile("ldmatrix.sync.aligned.m8n8.x2.shared.b16 {%0,%1}, [%2];"
                 : "=r"(r[0]), "=r"(r[1]) : "r"(addr));
}

// ---------------------------------------------------------------------------
// tf32 mma.sync GEMM: C[M,N] = A[M,512] @ W[N,512]^T (+bias, +epilogue)
// CTA: 128x128 tile, 256 threads = 8 warps (2 M x 4 N), warp = 64x32.
// R11 staging (float4 LDG + register prefetch); fragment loads via ldmatrix:
// per k8, 4 LDSM.x4 + 4 LDSM.x2 (was 24 LDS.32). Row stride 36 words == 4
// (mod 32) -> every 8-row x 4-word tile covers all 32 banks once.
// MODE 0: A = x,    epilogue = silu(.)+scatter to gate/q/k/v  (N = 2048)
// MODE 1: A = g_ng, epilogue = +b2 -> out                     (N = 512)
// ---------------------------------------------------------------------------
#define KST 36
template<int MODE>
__global__ void __launch_bounds__(256) tc_gemm(
    const float* __restrict__ A_in,
    const float* __restrict__ W,
    const float* __restrict__ bias,
    float* __restrict__ out)
{
    __shared__ uint32_t As[128][KST];   // [m][k] tf32 bits
    __shared__ uint32_t Bs[128][KST];   // [n][k] tf32 bits

    const float* A = (MODE == 0) ? A_in : g_ng;
    const int tid  = threadIdx.x;
    const int wid  = tid >> 5;
    const int lane = tid & 31;
    const int g    = lane >> 2;
    const int t    = lane & 3;
    const int row0 = blockIdx.y * 128;
    const int col0 = blockIdx.x * 128;
    const int wm   = (wid >> 2) * 64;
    const int wn   = (wid & 3) * 32;

    // ldmatrix per-lane source addresses
    const int arow = lane & 15;              // x4: lanes 0-15 rows, 16-31 rows(+w4)
    const int awrd = (lane >> 4) << 2;
    const int brow = lane & 7;               // x2: lanes 0-7 w0, 8-15 w4
    const int bwrd = ((lane >> 3) & 1) << 2;
    const uint32_t aAddr0 = smem_u32(As) + (((wm + arow) * KST) + awrd) * 4;
    const uint32_t bAddr0 = smem_u32(Bs) + (((wn + brow) * KST) + bwrd) * 4;

    float acc[4][4][4];
    #pragma unroll
    for (int i = 0; i < 4; i++)
        #pragma unroll
        for (int j = 0; j < 4; j++)
            #pragma unroll
            for (int q = 0; q < 4; q++) acc[i][j][q] = 0.0f;

    // prefetch K-block 0 (R11 coalesced float4 staging)
    float4 pa[4], pb[4];
    #pragma unroll
    for (int l = 0; l < 4; l++) {
        const int idx = tid + l * 256;
        const int r   = idx >> 3;
        const int c4  = (idx & 7) << 2;
        pa[l] = *(const float4*)&A[(size_t)(row0 + r) * 512 + c4];
        pb[l] = *(const float4*)&W[(size_t)(col0 + r) * 512 + c4];
    }

    for (int kb = 0; kb < 16; kb++) {
        // store prefetched block (cvt to tf32)
        #pragma unroll
        for (int l = 0; l < 4; l++) {
            const int idx = tid + l * 256;
            const int r   = idx >> 3;
            const int c4  = (idx & 7) << 2;
            *(uint4*)&As[r][c4] =
                make_uint4(f2tf(pa[l].x), f2tf(pa[l].y), f2tf(pa[l].z), f2tf(pa[l].w));
            *(uint4*)&Bs[r][c4] =
                make_uint4(f2tf(pb[l].x), f2tf(pb[l].y), f2tf(pb[l].z), f2tf(pb[l].w));
        }
        __syncthreads();

        // prefetch next block; latency hides under MMA loop below
        if (kb < 15) {
            const int k0 = (kb + 1) * 32;
            #pragma unroll
            for (int l = 0; l < 4; l++) {
                const int idx = tid + l * 256;
                const int r   = idx >> 3;
                const int c4  = (idx & 7) << 2;
                pa[l] = *(const float4*)&A[(size_t)(row0 + r) * 512 + k0 + c4];
                pb[l] = *(const float4*)&W[(size_t)(col0 + r) * 512 + k0 + c4];
            }
        }

        #pragma unroll
        for (int k8 = 0; k8 < 4; k8++) {
            uint32_t af[4][4];
            #pragma unroll
            for (int mt = 0; mt < 4; mt++)
                ldsm_x4(af[mt], aAddr0 + mt * (16 * KST * 4) + k8 * 32);
            uint32_t bf[4][2];
            #pragma unroll
            for (int nt = 0; nt < 4; nt++)
                ldsm_x2(bf[nt], bAddr0 + nt * (8 * KST * 4) + k8 * 32);
            #pragma unroll
            for (int mt = 0; mt < 4; mt++)
                #pragma unroll
                for (int nt = 0; nt < 4; nt++)
                    mma_tf32(acc[mt][nt], af[mt], bf[nt]);
        }
        __syncthreads();
    }

    #pragma unroll
    for (int mt = 0; mt < 4; mt++) {
        #pragma unroll
        for (int half = 0; half < 2; half++) {
            const int r = row0 + wm + mt * 16 + g + half * 8;
            const int b = r >> 11;
            const int s = r & 2047;
            #pragma unroll
            for (int nt = 0; nt < 4; nt++) {
                const int j = col0 + wn + nt * 8 + 2 * t;
                float2 v;
                v.x = acc[mt][nt][half * 2 + 0] + __ldg(&bias[j]);
                v.y = acc[mt][nt][half * 2 + 1] + __ldg(&bias[j + 1]);
                if (MODE == 0) {
                    v.x = silu_f(v.x);
                    v.y = silu_f(v.y);
                    const int c   = j >> 9;
                    const int rem = j & 511;
                    if (c == 0) {
                        *(float2*)&g_gate[(size_t)r * 512 + rem] = v;
                    } else {
                        const int head = rem >> 6;
                        const int d    = rem & 63;
                        float* dst = (c == 1) ? g_q : ((c == 2) ? g_k : g_v);
                        *(float2*)&dst[((size_t)(b * 8 + head) * 2048 + s) * 64 + d] = v;
                    }
                } else {
                    *(float2*)&out[(size_t)r * 512 + j] = v;
                }
            }
        }
    }
}

// ---------------------------------------------------------------------------
// Causal HSTU attention on tf32 mma.sync (R11 structure, known-good 406us),
// fragment loads via ldmatrix (6 LDSM per k8, was 16 LDS.32).
// Block: 256 thr = 8 warps (4 M x 2 N), 128-query tile per block. Register
// prefetch of next K/V tile overlaps LDG latency with the MMA loops.
// ---------------------------------------------------------------------------
#define AQST 68   // smem word stride; 68 mod 32 = 4 -> conflict-free tiles

__global__ void __launch_bounds__(256) attn_mma_kernel() {
    extern __shared__ uint32_t smw[];
    uint32_t* Qs = smw;                  // [128][AQST] tf32 [query][dim]
    uint32_t* Ks = smw + 128 * AQST;     // [64][AQST]  tf32 [key][dim]
    uint32_t* Vt = smw + 192 * AQST;     // [64][AQST]  tf32 [dim][key]
    uint32_t* St = smw + 256 * AQST;     // [128][AQST] tf32 [query][key]

    const int tid  = threadIdx.x;
    const int wid  = tid >> 5;
    const int lane = tid & 31;
    const int g    = lane >> 2;
    const int t    = lane & 3;
    const int qt   = blockIdx.x;         // 0..15 (128-query tiles)
    const int bh   = blockIdx.y;
    const int b    = bh >> 3;
    const int h    = bh & 7;
    const size_t base = (size_t)bh * SS * HD;
    const float* qp = g_q + base;
    const float* kp = g_k + base;
    const float* vp = g_v + base;
    const int s0 = qt * 128;
    const int wm = (wid >> 1) * 32;      // query offset: 0,32,64,96
    const int wn = (wid & 1) * 32;       // key/dim offset: 0,32

    // ldmatrix per-lane source addresses
    const int arow = lane & 15;
    const int awrd = (lane >> 4) << 2;
    const int brow = lane & 7;
    const int bwrd = ((lane >> 3) & 1) << 2;
    const uint32_t qAddr0 = smem_u32(Qs) + (((wm + arow) * AQST) + awrd) * 4;
    const uint32_t kAddr0 = smem_u32(Ks) + (((wn + brow) * AQST) + bwrd) * 4;
    const uint32_t sAddr0 = smem_u32(St) + (((wm + arow) * AQST) + awrd) * 4;
    const uint32_t vAddr0 = smem_u32(Vt) + (((wn + brow) * AQST) + bwrd) * 4;

    // Stage Q (128 x 64, tf32)
    #pragma unroll
    for (int l = 0; l < 8; l++) {
        const int idx = tid + l * 256;
        const int r   = idx >> 4;
        const int c4  = (idx & 15) << 2;
        float4 qv = *(const float4*)&qp[(size_t)(s0 + r) * 64 + c4];
        *(uint4*)&Qs[r * AQST + c4] =
            make_uint4(f2tf(qv.x), f2tf(qv.y), f2tf(qv.z), f2tf(qv.w));
    }

    float oacc[2][4][4];
    #pragma unroll
    for (int m = 0; m < 2; m++)
        #pragma unroll
        for (int i = 0; i < 4; i++)
            #pragma unroll
            for (int j = 0; j < 4; j++) oacc[m][i][j] = 0.0f;

    const int last = 2 * qt + 1;

    // prefetch K/V tile 0
    float4 pk[4], pv[4];
    #pragma unroll
    for (int l = 0; l < 4; l++) {
        const int idx = tid + l * 256;
        const int r   = idx >> 4;
        const int c4  = (idx & 15) << 2;
        pk[l] = *(const float4*)&kp[(size_t)r * 64 + c4];
        pv[l] = *(const float4*)&vp[(size_t)r * 64 + c4];
    }

    for (int kt = 0; kt <= last; kt++) {
        const int t0 = kt * 64;
        __syncthreads();   // prev-iter Ks/Vt/St reads done (and Qs staged, kt=0)

        // store prefetched K ([key][dim]) and V transposed ([dim][key])
        #pragma unroll
        for (int l = 0; l < 4; l++) {
            const int idx = tid + l * 256;
            const int r   = idx >> 4;
            const int c4  = (idx & 15) << 2;
            *(uint4*)&Ks[r * AQST + c4] =
                make_uint4(f2tf(pk[l].x), f2tf(pk[l].y), f2tf(pk[l].z), f2tf(pk[l].w));
            Vt[(c4 + 0) * AQST + r] = f2tf(pv[l].x);
            Vt[(c4 + 1) * AQST + r] = f2tf(pv[l].y);
            Vt[(c4 + 2) * AQST + r] = f2tf(pv[l].z);
            Vt[(c4 + 3) * AQST + r] = f2tf(pv[l].w);
        }
        __syncthreads();

        // prefetch next K/V tile; latency hides under the MMA loops
        if (kt < last) {
            const int tn = (kt + 1) * 64;
            #pragma unroll
            for (int l = 0; l < 4; l++) {
                const int idx = tid + l * 256;
                const int r   = idx >> 4;
                const int c4  = (idx & 15) << 2;
                pk[l] = *(const float4*)&kp[(size_t)(tn + r) * 64 + c4];
                pv[l] = *(const float4*)&vp[(size_t)(tn + r) * 64 + c4];
            }
        }

        // ---- GEMM 1: scores = Q @ K^T (per warp: M=32 queries, N=32 keys)
        float sacc[2][4][4];
        #pragma unroll
        for (int m = 0; m < 2; m++)
            #pragma unroll
            for (int i = 0; i < 4; i++)
                #pragma unroll
                for (int j = 0; j < 4; j++) sacc[m][i][j] = 0.0f;

        #pragma unroll
        for (int k8 = 0; k8 < 8; k8++) {
            uint32_t af[2][4];
            #pragma unroll
            for (int mt = 0; mt < 2; mt++)
                ldsm_x4(af[mt], qAddr0 + mt * (16 * AQST * 4) + k8 * 32);
            uint32_t bf[4][2];
            #pragma unroll
            for (int nt = 0; nt < 4; nt++)
                ldsm_x2(bf[nt], kAddr0 + nt * (8 * AQST * 4) + k8 * 32);
            #pragma unroll
            for (int mt = 0; mt < 2; mt++)
                #pragma unroll
                for (int nt = 0; nt < 4; nt++)
                    mma_tf32(sacc[mt][nt], af[mt], bf[nt]);
        }

        // silu + causal mask on fragments, re-round to tf32 into St
        const bool diag = (kt >= 2 * qt);
        #pragma unroll
        for (int mt = 0; mt < 2; mt++) {
            #pragma unroll
            for (int nt = 0; nt < 4; nt++) {
                const int klocal = wn + nt * 8 + 2 * t;
                const int key    = t0 + klocal;
                #pragma unroll
                for (int half = 0; half < 2; half++) {
                    const int qlocal = wm + mt * 16 + g + half * 8;
                    const int qrow   = s0 + qlocal;
                    float v0 = silu_f(sacc[mt][nt][half * 2 + 0] * 0.125f);
                    float v1 = silu_f(sacc[mt][nt][half * 2 + 1] * 0.125f);
                    if (diag) {
                        if (key     > qrow) v0 = 0.0f;
                        if (key + 1 > qrow) v1 = 0.0f;
                    }
                    *(uint2*)&St[qlocal * AQST + klocal] =
                        make_uint2(f2tf(v0), f2tf(v1));
                }
            }
        }
        __syncthreads();

        // ---- GEMM 2: O += St @ V  (A=St [query][key], B=Vt [dim][key])
        #pragma unroll
        for (int k8 = 0; k8 < 8; k8++) {
            uint32_t af[2][4];
            #pragma unroll
            for (int mt = 0; mt < 2; mt++)
                ldsm_x4(af[mt], sAddr0 + mt * (16 * AQST * 4) + k8 * 32);
            uint32_t bf[4][2];
            #pragma unroll
            for (int nt = 0; nt < 4; nt++)
                ldsm_x2(bf[nt], vAddr0 + nt * (8 * AQST * 4) + k8 * 32);
            #pragma unroll
            for (int mt = 0; mt < 2; mt++)
                #pragma unroll
                for (int nt = 0; nt < 4; nt++)
                    mma_tf32(oacc[mt][nt], af[mt], bf[nt]);
        }
    }

    // Write O in [b, s, h*64+dim] layout
    #pragma unroll
    for (int mt = 0; mt < 2; mt++) {
        #pragma unroll
        for (int nt = 0; nt < 4; nt++) {
            const int dim = wn + nt * 8 + 2 * t;
            #pragma unroll
            for (int half = 0; half < 2; half++) {
                const int srow = s0 + wm + mt * 16 + g + half * 8;
                float2 ov = make_float2(oacc[mt][nt][half * 2 + 0],
                                        oacc[mt][nt][half * 2 + 1]);
                *(float2*)&g_o[((size_t)(b * SS + srow)) * DD + h * 64 + dim] = ov;
            }
        }
    }
}

// ---------------------------------------------------------------------------
// LayerNorm(o) * gate  -> g_ng
// ---------------------------------------------------------------------------
__global__ void __launch_bounds__(128) ln_gate_kernel(
    const float* __restrict__ lng, const float* __restrict__ lnb)
{
    const int row = blockIdx.x;
    const int tid = threadIdx.x;
    const float* op = g_o + (size_t)row * DD;

    float4 x = *(const float4*)&op[tid * 4];
    float s = x.x + x.y + x.z + x.w;

    const int lane = tid & 31, wid = tid >> 5;
    __shared__ float r1[4], r2[4];

    #pragma unroll
    for (int off = 16; off; off >>= 1) s += __shfl_xor_sync(0xffffffffu, s, off);
    if (lane == 0) r1[wid] = s;
    __syncthreads();
    const float m = (r1[0] + r1[1] + r1[2] + r1[3]) * (1.0f / 512.0f);

    const float dx = x.x - m, dy = x.y - m, dz = x.z - m, dw = x.w - m;
    float sq = dx * dx + dy * dy + dz * dz + dw * dw;
    #pragma unroll
    for (int off = 16; off; off >>= 1) sq += __shfl_xor_sync(0xffffffffu, sq, off);
    if (lane == 0) r2[wid] = sq;
    __syncthreads();
    const float var = (r2[0] + r2[1] + r2[2] + r2[3]) * (1.0f / 512.0f);
    const float inv = rsqrtf(var + 1e-5f);

    float4 gv = *(const float4*)&lng[tid * 4];
    float4 bv = *(const float4*)&lnb[tid * 4];
    float4 gg = *(const float4*)&g_gate[(size_t)row * DD + tid * 4];
    float4 o;
    o.x = (dx * inv * gv.x + bv.x) * gg.x;
    o.y = (dy * inv * gv.y + bv.y) * gg.y;
    o.z = (dz * inv * gv.z + bv.z) * gg.z;
    o.w = (dw * inv * gv.w + bv.w) * gg.w;
    *(float4*)&g_ng[(size_t)row * DD + tid * 4] = o;
}

// ---------------------------------------------------------------------------
extern "C" void kernel_launch(void* const* d_in, const int* in_sizes, int n_in,
                              void* d_out, int out_size) {
    const float* x   = (const float*)d_in[0];
    const float* W1  = (const float*)d_in[1];
    const float* b1  = (const float*)d_in[2];
    const float* lng = (const float*)d_in[3];
    const float* lnb = (const float*)d_in[4];
    const float* W2  = (const float*)d_in[5];
    const float* b2  = (const float*)d_in[6];
    float* out = (float*)d_out;

    const int attn_smem = 384 * AQST * (int)sizeof(uint32_t);      // 104448 B
    cudaFuncSetAttribute(attn_mma_kernel,
                         cudaFuncAttributeMaxDynamicSharedMemorySize, attn_smem);

    // 1) h = silu(x @ W1^T + b1), scattered to gate/q/k/v   (tf32 mma.sync)
    tc_gemm<0><<<dim3(2048 / 128, MROWS / 128), 256>>>(x, W1, b1, out);

    // 2) causal silu-attention -> g_o [b,s,d]               (tf32 mma.sync)
    attn_mma_kernel<<<dim3(SS / 128, BB * HH), 256, attn_smem>>>();

    // 3) layernorm(o) * gate -> g_ng
    ln_gate_kernel<<<MROWS, 128>>>(lng, lnb);

    // 4) out = g_ng @ W2^T + b2                             (tf32 mma.sync)
    tc_gemm<1><<<dim3(512 / 128, MROWS / 128), 256>>>(nullptr, W2, b2, out);
}

// round 15
// speedup vs baseline: 1.4165x; 1.0684x over previous
#include <cuda_runtime.h>
#include <cstdint>

// Problem constants
#define BB 4
#define SS 2048
#define DD 512
#define HH 8
#define HD 64
#define MROWS (BB*SS)   // 8192

// Scratch (static device arrays -- allocation-free per harness rules)
__device__ float g_gate[BB*SS*DD];       // [b,s,d]
__device__ float g_q[BB*HH*SS*HD];       // [b,h,s,d]
__device__ float g_k[BB*HH*SS*HD];
__device__ float g_v[BB*HH*SS*HD];
__device__ float g_o[BB*SS*DD];          // [b,s,d]
__device__ float g_ng[BB*SS*DD];         // layernorm(o) * gate

__device__ __forceinline__ float silu_f(float x) {
    return __fdividef(x, 1.0f + __expf(-x));
}
__device__ __forceinline__ uint32_t f2tf(float x) {
    uint32_t r; asm("cvt.rna.tf32.f32 %0, %1;" : "=r"(r) : "f"(x)); return r;
}
__device__ __forceinline__ uint32_t smem_u32(const void* p) {
    uint32_t a;
    asm("{ .reg .u64 t; cvta.to.shared.u64 t, %1; cvt.u32.u64 %0, t; }"
        : "=r"(a) : "l"(p));
    return a;
}
// D = A(16x8,row) * B(8x8,col) + D, tf32 in, f32 accum
__device__ __forceinline__ void mma_tf32(float* c, const uint32_t* a, const uint32_t* b) {
    asm volatile(
        "mma.sync.aligned.m16n8k8.row.col.f32.tf32.tf32.f32 "
        "{%0,%1,%2,%3}, {%4,%5,%6,%7}, {%8,%9}, {%0,%1,%2,%3};"
        : "+f"(c[0]), "+f"(c[1]), "+f"(c[2]), "+f"(c[3])
        : "r"(a[0]), "r"(a[1]), "r"(a[2]), "r"(a[3]), "r"(b[0]), "r"(b[1]));
}
// ldmatrix: 4x (8 rows x 16B) tiles -> full tf32 m16n8k8 A fragment.
__device__ __forceinline__ void ldsm_x4(uint32_t* r, uint32_t addr) {
    asm volatile("ldmatrix.sync.aligned.m8n8.x4.shared.b16 {%0,%1,%2,%3}, [%4];"
                 : "=r"(r[0]), "=r"(r[1]), "=r"(r[2]), "=r"(r[3]) : "r"(addr));
}
// 2 tiles -> tf32 m16n8k8 B fragment (col-major B stored as [n][k]).
__device__ __forceinline__ void ldsm_x2(uint32_t* r, uint32_t addr) {
    asm volatile("ldmatrix.sync.aligned.m8n8.x2.shared.b16 {%0,%1}, [%2];"
                 : "=r"(r[0]), "=r"(r[1]) : "r"(addr));
}

// ---------------------------------------------------------------------------
// tf32 mma.sync GEMM: C[M,N] = A[M,512] @ W[N,512]^T (+bias, +epilogue)
// (unchanged from R14 -- measured at tf32 HMMA plateau)
// ---------------------------------------------------------------------------
#define KST 36
template<int MODE>
__global__ void __launch_bounds__(256) tc_gemm(
    const float* __restrict__ A_in,
    const float* __restrict__ W,
    const float* __restrict__ bias,
    float* __restrict__ out)
{
    __shared__ uint32_t As[128][KST];   // [m][k] tf32 bits
    __shared__ uint32_t Bs[128][KST];   // [n][k] tf32 bits

    const float* A = (MODE == 0) ? A_in : g_ng;
    const int tid  = threadIdx.x;
    const int wid  = tid >> 5;
    const int lane = tid & 31;
    const int g    = lane >> 2;
    const int t    = lane & 3;
    const int row0 = blockIdx.y * 128;
    const int col0 = blockIdx.x * 128;
    const int wm   = (wid >> 2) * 64;
    const int wn   = (wid & 3) * 32;

    const int arow = lane & 15;
    const int awrd = (lane >> 4) << 2;
    const int brow = lane & 7;
    const int bwrd = ((lane >> 3) & 1) << 2;
    const uint32_t aAddr0 = smem_u32(As) + (((wm + arow) * KST) + awrd) * 4;
    const uint32_t bAddr0 = smem_u32(Bs) + (((wn + brow) * KST) + bwrd) * 4;

    float acc[4][4][4];
    #pragma unroll
    for (int i = 0; i < 4; i++)
        #pragma unroll
        for (int j = 0; j < 4; j++)
            #pragma unroll
            for (int q = 0; q < 4; q++) acc[i][j][q] = 0.0f;

    float4 pa[4], pb[4];
    #pragma unroll
    for (int l = 0; l < 4; l++) {
        const int idx = tid + l * 256;
        const int r   = idx >> 3;
        const int c4  = (idx & 7) << 2;
        pa[l] = *(const float4*)&A[(size_t)(row0 + r) * 512 + c4];
        pb[l] = *(const float4*)&W[(size_t)(col0 + r) * 512 + c4];
    }

    for (int kb = 0; kb < 16; kb++) {
        #pragma unroll
        for (int l = 0; l < 4; l++) {
            const int idx = tid + l * 256;
            const int r   = idx >> 3;
            const int c4  = (idx & 7) << 2;
            *(uint4*)&As[r][c4] =
                make_uint4(f2tf(pa[l].x), f2tf(pa[l].y), f2tf(pa[l].z), f2tf(pa[l].w));
            *(uint4*)&Bs[r][c4] =
                make_uint4(f2tf(pb[l].x), f2tf(pb[l].y), f2tf(pb[l].z), f2tf(pb[l].w));
        }
        __syncthreads();

        if (kb < 15) {
            const int k0 = (kb + 1) * 32;
            #pragma unroll
            for (int l = 0; l < 4; l++) {
                const int idx = tid + l * 256;
                const int r   = idx >> 3;
                const int c4  = (idx & 7) << 2;
                pa[l] = *(const float4*)&A[(size_t)(row0 + r) * 512 + k0 + c4];
                pb[l] = *(const float4*)&W[(size_t)(col0 + r) * 512 + k0 + c4];
            }
        }

        #pragma unroll
        for (int k8 = 0; k8 < 4; k8++) {
            uint32_t af[4][4];
            #pragma unroll
            for (int mt = 0; mt < 4; mt++)
                ldsm_x4(af[mt], aAddr0 + mt * (16 * KST * 4) + k8 * 32);
            uint32_t bf[4][2];
            #pragma unroll
            for (int nt = 0; nt < 4; nt++)
                ldsm_x2(bf[nt], bAddr0 + nt * (8 * KST * 4) + k8 * 32);
            #pragma unroll
            for (int mt = 0; mt < 4; mt++)
                #pragma unroll
                for (int nt = 0; nt < 4; nt++)
                    mma_tf32(acc[mt][nt], af[mt], bf[nt]);
        }
        __syncthreads();
    }

    #pragma unroll
    for (int mt = 0; mt < 4; mt++) {
        #pragma unroll
        for (int half = 0; half < 2; half++) {
            const int r = row0 + wm + mt * 16 + g + half * 8;
            const int b = r >> 11;
            const int s = r & 2047;
            #pragma unroll
            for (int nt = 0; nt < 4; nt++) {
                const int j = col0 + wn + nt * 8 + 2 * t;
                float2 v;
                v.x = acc[mt][nt][half * 2 + 0] + __ldg(&bias[j]);
                v.y = acc[mt][nt][half * 2 + 1] + __ldg(&bias[j + 1]);
                if (MODE == 0) {
                    v.x = silu_f(v.x);
                    v.y = silu_f(v.y);
                    const int c   = j >> 9;
                    const int rem = j & 511;
                    if (c == 0) {
                        *(float2*)&g_gate[(size_t)r * 512 + rem] = v;
                    } else {
                        const int head = rem >> 6;
                        const int d    = rem & 63;
                        float* dst = (c == 1) ? g_q : ((c == 2) ? g_k : g_v);
                        *(float2*)&dst[((size_t)(b * 8 + head) * 2048 + s) * 64 + d] = v;
                    }
                } else {
                    *(float2*)&out[(size_t)r * 512 + j] = v;
                }
            }
        }
    }
}

// ---------------------------------------------------------------------------
// Causal HSTU attention on tf32 mma.sync (R14 body) with BALANCED PAIR
// SCHEDULING: grid = 256 CTAs; CTA (bh, pa) processes query tiles
// qt = 15-pa (heavy) then qt = pa (light). Per-CTA work = 34 key-tiles,
// exactly constant -> one perfectly balanced wave (256 <= 2 CTA/SM * 148).
// ---------------------------------------------------------------------------
#define AQST 68   // smem word stride; 68 mod 32 = 4 -> conflict-free tiles

__global__ void __launch_bounds__(256) attn_mma_kernel() {
    extern __shared__ uint32_t smw[];
    uint32_t* Qs = smw;                  // [128][AQST] tf32 [query][dim]
    uint32_t* Ks = smw + 128 * AQST;     // [64][AQST]  tf32 [key][dim]
    uint32_t* Vt = smw + 192 * AQST;     // [64][AQST]  tf32 [dim][key]
    uint32_t* St = smw + 256 * AQST;     // [128][AQST] tf32 [query][key]

    const int tid  = threadIdx.x;
    const int wid  = tid >> 5;
    const int lane = tid & 31;
    const int g    = lane >> 2;
    const int t    = lane & 3;
    const int cta  = blockIdx.x;         // 0..255
    const int bh   = cta >> 3;           // 0..31
    const int pa   = cta & 7;            // 0..7
    const int b    = bh >> 3;
    const int h    = bh & 7;
    const size_t base = (size_t)bh * SS * HD;
    const float* qp = g_q + base;
    const float* kp = g_k + base;
    const float* vp = g_v + base;
    const int wm = (wid >> 1) * 32;      // query offset: 0,32,64,96
    const int wn = (wid & 1) * 32;       // key/dim offset: 0,32

    const int arow = lane & 15;
    const int awrd = (lane >> 4) << 2;
    const int brow = lane & 7;
    const int bwrd = ((lane >> 3) & 1) << 2;
    const uint32_t qAddr0 = smem_u32(Qs) + (((wm + arow) * AQST) + awrd) * 4;
    const uint32_t kAddr0 = smem_u32(Ks) + (((wn + brow) * AQST) + bwrd) * 4;
    const uint32_t sAddr0 = smem_u32(St) + (((wm + arow) * AQST) + awrd) * 4;
    const uint32_t vAddr0 = smem_u32(Vt) + (((wn + brow) * AQST) + bwrd) * 4;

    #pragma unroll 1
    for (int sub = 0; sub < 2; sub++) {
        const int qt = sub ? pa : (15 - pa);   // heavy tile first
        const int s0 = qt * 128;
        const int last = 2 * qt + 1;

        __syncthreads();   // protect Qs/St/Ks/Vt from previous sub-tile reads

        // Stage Q (128 x 64, tf32)
        #pragma unroll
        for (int l = 0; l < 8; l++) {
            const int idx = tid + l * 256;
            const int r   = idx >> 4;
            const int c4  = (idx & 15) << 2;
            float4 qv = *(const float4*)&qp[(size_t)(s0 + r) * 64 + c4];
            *(uint4*)&Qs[r * AQST + c4] =
                make_uint4(f2tf(qv.x), f2tf(qv.y), f2tf(qv.z), f2tf(qv.w));
        }

        float oacc[2][4][4];
        #pragma unroll
        for (int m = 0; m < 2; m++)
            #pragma unroll
            for (int i = 0; i < 4; i++)
                #pragma unroll
                for (int j = 0; j < 4; j++) oacc[m][i][j] = 0.0f;

        // prefetch K/V tile 0
        float4 pk[4], pv[4];
        #pragma unroll
        for (int l = 0; l < 4; l++) {
            const int idx = tid + l * 256;
            const int r   = idx >> 4;
            const int c4  = (idx & 15) << 2;
            pk[l] = *(const float4*)&kp[(size_t)r * 64 + c4];
            pv[l] = *(const float4*)&vp[(size_t)r * 64 + c4];
        }

        for (int kt = 0; kt <= last; kt++) {
            const int t0 = kt * 64;
            __syncthreads();   // prev-iter Ks/Vt/St reads done (and Qs staged)

            // store prefetched K ([key][dim]) and V transposed ([dim][key])
            #pragma unroll
            for (int l = 0; l < 4; l++) {
                const int idx = tid + l * 256;
                const int r   = idx >> 4;
                const int c4  = (idx & 15) << 2;
                *(uint4*)&Ks[r * AQST + c4] =
                    make_uint4(f2tf(pk[l].x), f2tf(pk[l].y), f2tf(pk[l].z), f2tf(pk[l].w));
                Vt[(c4 + 0) * AQST + r] = f2tf(pv[l].x);
                Vt[(c4 + 1) * AQST + r] = f2tf(pv[l].y);
                Vt[(c4 + 2) * AQST + r] = f2tf(pv[l].z);
                Vt[(c4 + 3) * AQST + r] = f2tf(pv[l].w);
            }
            __syncthreads();

            // prefetch next K/V tile; latency hides under the MMA loops
            if (kt < last) {
                const int tn = (kt + 1) * 64;
                #pragma unroll
                for (int l = 0; l < 4; l++) {
                    const int idx = tid + l * 256;
                    const int r   = idx >> 4;
                    const int c4  = (idx & 15) << 2;
                    pk[l] = *(const float4*)&kp[(size_t)(tn + r) * 64 + c4];
                    pv[l] = *(const float4*)&vp[(size_t)(tn + r) * 64 + c4];
                }
            }

            // ---- GEMM 1: scores = Q @ K^T (per warp: M=32, N=32)
            float sacc[2][4][4];
            #pragma unroll
            for (int m = 0; m < 2; m++)
                #pragma unroll
                for (int i = 0; i < 4; i++)
                    #pragma unroll
                    for (int j = 0; j < 4; j++) sacc[m][i][j] = 0.0f;

            #pragma unroll
            for (int k8 = 0; k8 < 8; k8++) {
                uint32_t af[2][4];
                #pragma unroll
                for (int mt = 0; mt < 2; mt++)
                    ldsm_x4(af[mt], qAddr0 + mt * (16 * AQST * 4) + k8 * 32);
                uint32_t bf[4][2];
                #pragma unroll
                for (int nt = 0; nt < 4; nt++)
                    ldsm_x2(bf[nt], kAddr0 + nt * (8 * AQST * 4) + k8 * 32);
                #pragma unroll
                for (int mt = 0; mt < 2; mt++)
                    #pragma unroll
                    for (int nt = 0; nt < 4; nt++)
                        mma_tf32(sacc[mt][nt], af[mt], bf[nt]);
            }

            // silu + causal mask on fragments, re-round to tf32 into St
            const bool diag = (kt >= 2 * qt);
            #pragma unroll
            for (int mt = 0; mt < 2; mt++) {
                #pragma unroll
                for (int nt = 0; nt < 4; nt++) {
                    const int klocal = wn + nt * 8 + 2 * t;
                    const int key    = t0 + klocal;
                    #pragma unroll
                    for (int half = 0; half < 2; half++) {
                        const int qlocal = wm + mt * 16 + g + half * 8;
                        const int qrow   = s0 + qlocal;
                        float v0 = silu_f(sacc[mt][nt][half * 2 + 0] * 0.125f);
                        float v1 = silu_f(sacc[mt][nt][half * 2 + 1] * 0.125f);
                        if (diag) {
                            if (key     > qrow) v0 = 0.0f;
                            if (key + 1 > qrow) v1 = 0.0f;
                        }
                        *(uint2*)&St[qlocal * AQST + klocal] =
                            make_uint2(f2tf(v0), f2tf(v1));
                    }
                }
            }
            __syncthreads();

            // ---- GEMM 2: O += St @ V  (A=St [query][key], B=Vt [dim][key])
            #pragma unroll
            for (int k8 = 0; k8 < 8; k8++) {
                uint32_t af[2][4];
                #pragma unroll
                for (int mt = 0; mt < 2; mt++)
                    ldsm_x4(af[mt], sAddr0 + mt * (16 * AQST * 4) + k8 * 32);
                uint32_t bf[4][2];
                #pragma unroll
                for (int nt = 0; nt < 4; nt++)
                    ldsm_x2(bf[nt], vAddr0 + nt * (8 * AQST * 4) + k8 * 32);
                #pragma unroll
                for (int mt = 0; mt < 2; mt++)
                    #pragma unroll
                    for (int nt = 0; nt < 4; nt++)
                        mma_tf32(oacc[mt][nt], af[mt], bf[nt]);
            }
        }

        // Write O in [b, s, h*64+dim] layout
        #pragma unroll
        for (int mt = 0; mt < 2; mt++) {
            #pragma unroll
            for (int nt = 0; nt < 4; nt++) {
                const int dim = wn + nt * 8 + 2 * t;
                #pragma unroll
                for (int half = 0; half < 2; half++) {
                    const int srow = s0 + wm + mt * 16 + g + half * 8;
                    float2 ov = make_float2(oacc[mt][nt][half * 2 + 0],
                                            oacc[mt][nt][half * 2 + 1]);
                    *(float2*)&g_o[((size_t)(b * SS + srow)) * DD + h * 64 + dim] = ov;
                }
            }
        }
    }
}

// ---------------------------------------------------------------------------
// LayerNorm(o) * gate  -> g_ng
// ---------------------------------------------------------------------------
__global__ void __launch_bounds__(128) ln_gate_kernel(
    const float* __restrict__ lng, const float* __restrict__ lnb)
{
    const int row = blockIdx.x;
    const int tid = threadIdx.x;
    const float* op = g_o + (size_t)row * DD;

    float4 x = *(const float4*)&op[tid * 4];
    float s = x.x + x.y + x.z + x.w;

    const int lane = tid & 31, wid = tid >> 5;
    __shared__ float r1[4], r2[4];

    #pragma unroll
    for (int off = 16; off; off >>= 1) s += __shfl_xor_sync(0xffffffffu, s, off);
    if (lane == 0) r1[wid] = s;
    __syncthreads();
    const float m = (r1[0] + r1[1] + r1[2] + r1[3]) * (1.0f / 512.0f);

    const float dx = x.x - m, dy = x.y - m, dz = x.z - m, dw = x.w - m;
    float sq = dx * dx + dy * dy + dz * dz + dw * dw;
    #pragma unroll
    for (int off = 16; off; off >>= 1) sq += __shfl_xor_sync(0xffffffffu, sq, off);
    if (lane == 0) r2[wid] = sq;
    __syncthreads();
    const float var = (r2[0] + r2[1] + r2[2] + r2[3]) * (1.0f / 512.0f);
    const float inv = rsqrtf(var + 1e-5f);

    float4 gv = *(const float4*)&lng[tid * 4];
    float4 bv = *(const float4*)&lnb[tid * 4];
    float4 gg = *(const float4*)&g_gate[(size_t)row * DD + tid * 4];
    float4 o;
    o.x = (dx * inv * gv.x + bv.x) * gg.x;
    o.y = (dy * inv * gv.y + bv.y) * gg.y;
    o.z = (dz * inv * gv.z + bv.z) * gg.z;
    o.w = (dw * inv * gv.w + bv.w) * gg.w;
    *(float4*)&g_ng[(size_t)row * DD + tid * 4] = o;
}

// ---------------------------------------------------------------------------
extern "C" void kernel_launch(void* const* d_in, const int* in_sizes, int n_in,
                              void* d_out, int out_size) {
    const float* x   = (const float*)d_in[0];
    const float* W1  = (const float*)d_in[1];
    const float* b1  = (const float*)d_in[2];
    const float* lng = (const float*)d_in[3];
    const float* lnb = (const float*)d_in[4];
    const float* W2  = (const float*)d_in[5];
    const float* b2  = (const float*)d_in[6];
    float* out = (float*)d_out;

    const int attn_smem = 384 * AQST * (int)sizeof(uint32_t);      // 104448 B
    cudaFuncSetAttribute(attn_mma_kernel,
                         cudaFuncAttributeMaxDynamicSharedMemorySize, attn_smem);

    // 1) h = silu(x @ W1^T + b1), scattered to gate/q/k/v   (tf32 mma.sync)
    tc_gemm<0><<<dim3(2048 / 128, MROWS / 128), 256>>>(x, W1, b1, out);

    // 2) causal silu-attention -> g_o [b,s,d]  (paired-balanced, one wave)
    attn_mma_kernel<<<256, 256, attn_smem>>>();

    // 3) layernorm(o) * gate -> g_ng
    ln_gate_kernel<<<MROWS, 128>>>(lng, lnb);

    // 4) out = g_ng @ W2^T + b2                             (tf32 mma.sync)
    tc_gemm<1><<<dim3(512 / 128, MROWS / 128), 256>>>(nullptr, W2, b2, out);
}

// round 16
// speedup vs baseline: 2.6231x; 1.8518x over previous
#include <cuda_runtime.h>
#include <cuda_fp16.h>
#include <cstdint>

// Problem constants
#define BB 4
#define SS 2048
#define DD 512
#define HH 8
#define HD 64
#define MROWS (BB*SS)   // 8192

// Scratch (static device arrays -- allocation-free per harness rules)
__device__ float  g_gate[BB*SS*DD];      // [b,s,d] fp32 (multiplies final output)
__device__ __half g_q[BB*HH*SS*HD];      // [b,h,s,d] fp16
__device__ __half g_k[BB*HH*SS*HD];
__device__ __half g_v[BB*HH*SS*HD];
__device__ float  g_o[BB*SS*DD];         // [b,s,d] fp32 (LN input)
__device__ float  g_ng[BB*SS*DD];        // layernorm(o) * gate, fp32

__device__ __forceinline__ float silu_f(float x) {
    return __fdividef(x, 1.0f + __expf(-x));
}
__device__ __forceinline__ uint32_t f2h2(float lo, float hi) {
    uint32_t r;
    asm("cvt.rn.f16x2.f32 %0, %2, %1;" : "=r"(r) : "f"(lo), "f"(hi));
    return r;
}
__device__ __forceinline__ uint32_t smem_u32(const void* p) {
    uint32_t a;
    asm("{ .reg .u64 t; cvta.to.shared.u64 t, %1; cvt.u32.u64 %0, t; }"
        : "=r"(a) : "l"(p));
    return a;
}
// D = A(16x16,row) * B(16x8,col) + D, fp16 in, f32 accum
__device__ __forceinline__ void mma_f16(float* c, const uint32_t* a, const uint32_t* b) {
    asm volatile(
        "mma.sync.aligned.m16n8k16.row.col.f32.f16.f16.f32 "
        "{%0,%1,%2,%3}, {%4,%5,%6,%7}, {%8,%9}, {%0,%1,%2,%3};"
        : "+f"(c[0]), "+f"(c[1]), "+f"(c[2]), "+f"(c[3])
        : "r"(a[0]), "r"(a[1]), "r"(a[2]), "r"(a[3]), "r"(b[0]), "r"(b[1]));
}
// 4x (8 rows x 16B) tiles -> fp16 m16n8k16 A fragment (rows 0-15, k 0-15).
__device__ __forceinline__ void ldsm_x4(uint32_t* r, uint32_t addr) {
    asm volatile("ldmatrix.sync.aligned.m8n8.x4.shared.b16 {%0,%1,%2,%3}, [%4];"
                 : "=r"(r[0]), "=r"(r[1]), "=r"(r[2]), "=r"(r[3]) : "r"(addr));
}
// 2 tiles -> fp16 m16n8k16 B fragment, B stored [n][k].
__device__ __forceinline__ void ldsm_x2(uint32_t* r, uint32_t addr) {
    asm volatile("ldmatrix.sync.aligned.m8n8.x2.shared.b16 {%0,%1}, [%2];"
                 : "=r"(r[0]), "=r"(r[1]) : "r"(addr));
}
// 2 tiles TRANSPOSED -> fp16 B fragment from matrix stored [k][n].
__device__ __forceinline__ void ldsm_x2t(uint32_t* r, uint32_t addr) {
    asm volatile("ldmatrix.sync.aligned.m8n8.x2.trans.shared.b16 {%0,%1}, [%2];"
                 : "=r"(r[0]), "=r"(r[1]) : "r"(addr));
}

// ---------------------------------------------------------------------------
// fp16 mma.sync GEMM: C[M,N] = A[M,512] @ W[N,512]^T (+bias, +epilogue)
// CTA: 128x128 tile, 256 threads = 8 warps (2 M x 4 N), warp = 64x32.
// m16n8k16: per 32-k block, 2 k16 steps x (4 LDSM.x4 + 4 LDSM.x2 + 16 MMA).
// Smem stride 40 halves (80 B, odd mult of 16 mod 128) -> conflict-free.
// MODE 0: A = x,    epilogue = silu(.)+scatter to gate(f32)/q,k,v(f16)
// MODE 1: A = g_ng, epilogue = +b2 -> out (f32)
// ---------------------------------------------------------------------------
#define KSTH 40
template<int MODE>
__global__ void __launch_bounds__(256) tc_gemm(
    const float* __restrict__ A_in,
    const float* __restrict__ W,
    const float* __restrict__ bias,
    float* __restrict__ out)
{
    __shared__ __half Ash[128 * KSTH];   // [m][k] fp16
    __shared__ __half Bsh[128 * KSTH];   // [n][k] fp16

    const float* A = (MODE == 0) ? A_in : g_ng;
    const int tid  = threadIdx.x;
    const int wid  = tid >> 5;
    const int lane = tid & 31;
    const int g    = lane >> 2;
    const int t    = lane & 3;
    const int row0 = blockIdx.y * 128;
    const int col0 = blockIdx.x * 128;
    const int wm   = (wid >> 2) * 64;
    const int wn   = (wid & 3) * 32;

    const uint32_t aAddr0 = smem_u32(Ash) +
        (((wm + (lane & 15)) * KSTH) + ((lane >> 4) << 3)) * 2;
    const uint32_t bAddr0 = smem_u32(Bsh) +
        (((wn + (lane & 7)) * KSTH) + (((lane >> 3) & 1) << 3)) * 2;

    float acc[4][4][4];
    #pragma unroll
    for (int i = 0; i < 4; i++)
        #pragma unroll
        for (int j = 0; j < 4; j++)
            #pragma unroll
            for (int q = 0; q < 4; q++) acc[i][j][q] = 0.0f;

    float4 pa[4], pb[4];
    #pragma unroll
    for (int l = 0; l < 4; l++) {
        const int idx = tid + l * 256;
        const int r   = idx >> 3;
        const int c4  = (idx & 7) << 2;
        pa[l] = *(const float4*)&A[(size_t)(row0 + r) * 512 + c4];
        pb[l] = *(const float4*)&W[(size_t)(col0 + r) * 512 + c4];
    }

    for (int kb = 0; kb < 16; kb++) {
        #pragma unroll
        for (int l = 0; l < 4; l++) {
            const int idx = tid + l * 256;
            const int r   = idx >> 3;
            const int c4  = (idx & 7) << 2;
            *(uint2*)&Ash[r * KSTH + c4] =
                make_uint2(f2h2(pa[l].x, pa[l].y), f2h2(pa[l].z, pa[l].w));
            *(uint2*)&Bsh[r * KSTH + c4] =
                make_uint2(f2h2(pb[l].x, pb[l].y), f2h2(pb[l].z, pb[l].w));
        }
        __syncthreads();

        if (kb < 15) {
            const int k0 = (kb + 1) * 32;
            #pragma unroll
            for (int l = 0; l < 4; l++) {
                const int idx = tid + l * 256;
                const int r   = idx >> 3;
                const int c4  = (idx & 7) << 2;
                pa[l] = *(const float4*)&A[(size_t)(row0 + r) * 512 + k0 + c4];
                pb[l] = *(const float4*)&W[(size_t)(col0 + r) * 512 + k0 + c4];
            }
        }

        #pragma unroll
        for (int k16 = 0; k16 < 2; k16++) {
            uint32_t af[4][4];
            #pragma unroll
            for (int mt = 0; mt < 4; mt++)
                ldsm_x4(af[mt], aAddr0 + mt * (16 * KSTH * 2) + k16 * 32);
            uint32_t bf[4][2];
            #pragma unroll
            for (int nt = 0; nt < 4; nt++)
                ldsm_x2(bf[nt], bAddr0 + nt * (8 * KSTH * 2) + k16 * 32);
            #pragma unroll
            for (int mt = 0; mt < 4; mt++)
                #pragma unroll
                for (int nt = 0; nt < 4; nt++)
                    mma_f16(acc[mt][nt], af[mt], bf[nt]);
        }
        __syncthreads();
    }

    #pragma unroll
    for (int mt = 0; mt < 4; mt++) {
        #pragma unroll
        for (int half = 0; half < 2; half++) {
            const int r = row0 + wm + mt * 16 + g + half * 8;
            const int b = r >> 11;
            const int s = r & 2047;
            #pragma unroll
            for (int nt = 0; nt < 4; nt++) {
                const int j = col0 + wn + nt * 8 + 2 * t;
                float2 v;
                v.x = acc[mt][nt][half * 2 + 0] + __ldg(&bias[j]);
                v.y = acc[mt][nt][half * 2 + 1] + __ldg(&bias[j + 1]);
                if (MODE == 0) {
                    v.x = silu_f(v.x);
                    v.y = silu_f(v.y);
                    const int c   = j >> 9;
                    const int rem = j & 511;
                    if (c == 0) {
                        *(float2*)&g_gate[(size_t)r * 512 + rem] = v;   // fp32
                    } else {
                        const int head = rem >> 6;
                        const int d    = rem & 63;
                        __half* dst = (c == 1) ? g_q : ((c == 2) ? g_k : g_v);
                        *(uint32_t*)&dst[((size_t)(b * 8 + head) * 2048 + s) * 64 + d] =
                            f2h2(v.x, v.y);                             // fp16
                    }
                } else {
                    *(float2*)&out[(size_t)r * 512 + j] = v;
                }
            }
        }
    }
}

// ---------------------------------------------------------------------------
// Causal HSTU attention, fp16 mma.sync, balanced pair scheduling (R15).
// Grid = 256 CTAs: CTA (bh, pa) does query tiles 15-pa then pa (34 key-tiles
// each, exactly constant). Q/K/V staged as raw fp16 uint4 copies (zero cvt);
// V kept natural [key][dim] and fed to GEMM2 via ldmatrix.trans.
// Smem stride 72 halves (144 B) -> conflict-free ldmatrix tiles.
// ---------------------------------------------------------------------------
#define ASTH 72

__global__ void __launch_bounds__(256) attn_mma_kernel() {
    extern __shared__ __half smh[];
    __half* Qs = smh;                    // [128][ASTH] fp16 [query][dim]
    __half* Ks = smh + 128 * ASTH;       // [64][ASTH]  fp16 [key][dim]
    __half* Vs = Ks + 64 * ASTH;         // [64][ASTH]  fp16 [key][dim] (natural)
    __half* St = Vs + 64 * ASTH;         // [128][ASTH] fp16 [query][key]

    const int tid  = threadIdx.x;
    const int wid  = tid >> 5;
    const int lane = tid & 31;
    const int g    = lane >> 2;
    const int t    = lane & 3;
    const int cta  = blockIdx.x;         // 0..255
    const int bh   = cta >> 3;           // 0..31
    const int pa   = cta & 7;            // 0..7
    const int b    = bh >> 3;
    const int h    = bh & 7;
    const size_t base = (size_t)bh * SS * HD;
    const __half* qp = g_q + base;
    const __half* kp = g_k + base;
    const __half* vp = g_v + base;
    const int wm = (wid >> 1) * 32;      // query offset: 0,32,64,96
    const int wn = (wid & 1) * 32;       // key/dim offset: 0,32

    const uint32_t qAddr0 = smem_u32(Qs) +
        (((wm + (lane & 15)) * ASTH) + ((lane >> 4) << 3)) * 2;
    const uint32_t kAddr0 = smem_u32(Ks) +
        (((wn + (lane & 7)) * ASTH) + (((lane >> 3) & 1) << 3)) * 2;
    const uint32_t sAddr0 = smem_u32(St) +
        (((wm + (lane & 15)) * ASTH) + ((lane >> 4) << 3)) * 2;
    const uint32_t vAddr0 = smem_u32(Vs) + (((lane & 15) * ASTH) + wn) * 2;

    #pragma unroll 1
    for (int sub = 0; sub < 2; sub++) {
        const int qt = sub ? pa : (15 - pa);   // heavy tile first
        const int s0 = qt * 128;
        const int last = 2 * qt + 1;

        __syncthreads();   // protect Qs/St/Ks/Vs from previous sub-tile reads

        // Stage Q (128 x 64 fp16): raw uint4 copies
        #pragma unroll
        for (int l = 0; l < 4; l++) {
            const int idx = tid + l * 256;
            const int r   = idx >> 3;
            const int c8  = (idx & 7) << 3;
            *(uint4*)&Qs[r * ASTH + c8] =
                *(const uint4*)&qp[(size_t)(s0 + r) * 64 + c8];
        }

        float oacc[2][4][4];
        #pragma unroll
        for (int m = 0; m < 2; m++)
            #pragma unroll
            for (int i = 0; i < 4; i++)
                #pragma unroll
                for (int j = 0; j < 4; j++) oacc[m][i][j] = 0.0f;

        // prefetch K/V tile 0 (raw fp16)
        uint4 pk[2], pv[2];
        #pragma unroll
        for (int l = 0; l < 2; l++) {
            const int idx = tid + l * 256;
            const int r   = idx >> 3;
            const int c8  = (idx & 7) << 3;
            pk[l] = *(const uint4*)&kp[(size_t)r * 64 + c8];
            pv[l] = *(const uint4*)&vp[(size_t)r * 64 + c8];
        }

        for (int kt = 0; kt <= last; kt++) {
            const int t0 = kt * 64;
            __syncthreads();   // prev-iter Ks/Vs/St reads done (and Qs staged)

            #pragma unroll
            for (int l = 0; l < 2; l++) {
                const int idx = tid + l * 256;
                const int r   = idx >> 3;
                const int c8  = (idx & 7) << 3;
                *(uint4*)&Ks[r * ASTH + c8] = pk[l];
                *(uint4*)&Vs[r * ASTH + c8] = pv[l];
            }
            __syncthreads();

            // prefetch next K/V tile; latency hides under the MMA loops
            if (kt < last) {
                const int tn = (kt + 1) * 64;
                #pragma unroll
                for (int l = 0; l < 2; l++) {
                    const int idx = tid + l * 256;
                    const int r   = idx >> 3;
                    const int c8  = (idx & 7) << 3;
                    pk[l] = *(const uint4*)&kp[(size_t)(tn + r) * 64 + c8];
                    pv[l] = *(const uint4*)&vp[(size_t)(tn + r) * 64 + c8];
                }
            }

            // ---- GEMM 1: scores = Q @ K^T (per warp: M=32, N=32; k=dim)
            float sacc[2][4][4];
            #pragma unroll
            for (int m = 0; m < 2; m++)
                #pragma unroll
                for (int i = 0; i < 4; i++)
                    #pragma unroll
                    for (int j = 0; j < 4; j++) sacc[m][i][j] = 0.0f;

            #pragma unroll
            for (int k16 = 0; k16 < 4; k16++) {
                uint32_t af[2][4];
                #pragma unroll
                for (int mt = 0; mt < 2; mt++)
                    ldsm_x4(af[mt], qAddr0 + mt * (16 * ASTH * 2) + k16 * 32);
                uint32_t bf[4][2];
                #pragma unroll
                for (int nt = 0; nt < 4; nt++)
                    ldsm_x2(bf[nt], kAddr0 + nt * (8 * ASTH * 2) + k16 * 32);
                #pragma unroll
                for (int mt = 0; mt < 2; mt++)
                    #pragma unroll
                    for (int nt = 0; nt < 4; nt++)
                        mma_f16(sacc[mt][nt], af[mt], bf[nt]);
            }

            // silu + causal mask on fragments, round to fp16 into St
            const bool diag = (kt >= 2 * qt);
            #pragma unroll
            for (int mt = 0; mt < 2; mt++) {
                #pragma unroll
                for (int nt = 0; nt < 4; nt++) {
                    const int klocal = wn + nt * 8 + 2 * t;
                    const int key    = t0 + klocal;
                    #pragma unroll
                    for (int half = 0; half < 2; half++) {
                        const int qlocal = wm + mt * 16 + g + half * 8;
                        const int qrow   = s0 + qlocal;
                        float v0 = silu_f(sacc[mt][nt][half * 2 + 0] * 0.125f);
                        float v1 = silu_f(sacc[mt][nt][half * 2 + 1] * 0.125f);
                        if (diag) {
                            if (key     > qrow) v0 = 0.0f;
                            if (key + 1 > qrow) v1 = 0.0f;
                        }
                        *(uint32_t*)&St[qlocal * ASTH + klocal] = f2h2(v0, v1);
                    }
                }
            }
            __syncthreads();

            // ---- GEMM 2: O += St @ V  (A=St [q][key]; B=Vs [key][dim] via
            //      ldmatrix.trans; k=key)
            #pragma unroll
            for (int k16 = 0; k16 < 4; k16++) {
                uint32_t af[2][4];
                #pragma unroll
                for (int mt = 0; mt < 2; mt++)
                    ldsm_x4(af[mt], sAddr0 + mt * (16 * ASTH * 2) + k16 * 32);
                uint32_t bf[4][2];
                #pragma unroll
                for (int nt = 0; nt < 4; nt++)
                    ldsm_x2t(bf[nt], vAddr0 + k16 * (16 * ASTH * 2) + nt * 16);
                #pragma unroll
                for (int mt = 0; mt < 2; mt++)
                    #pragma unroll
                    for (int nt = 0; nt < 4; nt++)
                        mma_f16(oacc[mt][nt], af[mt], bf[nt]);
            }
        }

        // Write O in [b, s, h*64+dim] layout (fp32)
        #pragma unroll
        for (int mt = 0; mt < 2; mt++) {
            #pragma unroll
            for (int nt = 0; nt < 4; nt++) {
                const int dim = wn + nt * 8 + 2 * t;
                #pragma unroll
                for (int half = 0; half < 2; half++) {
                    const int srow = s0 + wm + mt * 16 + g + half * 8;
                    float2 ov = make_float2(oacc[mt][nt][half * 2 + 0],
                                            oacc[mt][nt][half * 2 + 1]);
                    *(float2*)&g_o[((size_t)(b * SS + srow)) * DD + h * 64 + dim] = ov;
                }
            }
        }
    }
}

// ---------------------------------------------------------------------------
// LayerNorm(o) * gate  -> g_ng   (all fp32, unchanged)
// ---------------------------------------------------------------------------
__global__ void __launch_bounds__(128) ln_gate_kernel(
    const float* __restrict__ lng, const float* __restrict__ lnb)
{
    const int row = blockIdx.x;
    const int tid = threadIdx.x;
    const float* op = g_o + (size_t)row * DD;

    float4 x = *(const float4*)&op[tid * 4];
    float s = x.x + x.y + x.z + x.w;

    const int lane = tid & 31, wid = tid >> 5;
    __shared__ float r1[4], r2[4];

    #pragma unroll
    for (int off = 16; off; off >>= 1) s += __shfl_xor_sync(0xffffffffu, s, off);
    if (lane == 0) r1[wid] = s;
    __syncthreads();
    const float m = (r1[0] + r1[1] + r1[2] + r1[3]) * (1.0f / 512.0f);

    const float dx = x.x - m, dy = x.y - m, dz = x.z - m, dw = x.w - m;
    float sq = dx * dx + dy * dy + dz * dz + dw * dw;
    #pragma unroll
    for (int off = 16; off; off >>= 1) sq += __shfl_xor_sync(0xffffffffu, sq, off);
    if (lane == 0) r2[wid] = sq;
    __syncthreads();
    const float var = (r2[0] + r2[1] + r2[2] + r2[3]) * (1.0f / 512.0f);
    const float inv = rsqrtf(var + 1e-5f);

    float4 gv = *(const float4*)&lng[tid * 4];
    float4 bv = *(const float4*)&lnb[tid * 4];
    float4 gg = *(const float4*)&g_gate[(size_t)row * DD + tid * 4];
    float4 o;
    o.x = (dx * inv * gv.x + bv.x) * gg.x;
    o.y = (dy * inv * gv.y + bv.y) * gg.y;
    o.z = (dz * inv * gv.z + bv.z) * gg.z;
    o.w = (dw * inv * gv.w + bv.w) * gg.w;
    *(float4*)&g_ng[(size_t)row * DD + tid * 4] = o;
}

// ---------------------------------------------------------------------------
extern "C" void kernel_launch(void* const* d_in, const int* in_sizes, int n_in,
                              void* d_out, int out_size) {
    const float* x   = (const float*)d_in[0];
    const float* W1  = (const float*)d_in[1];
    const float* b1  = (const float*)d_in[2];
    const float* lng = (const float*)d_in[3];
    const float* lnb = (const float*)d_in[4];
    const float* W2  = (const float*)d_in[5];
    const float* b2  = (const float*)d_in[6];
    float* out = (float*)d_out;

    const int attn_smem = 384 * ASTH * (int)sizeof(__half);   // 55296 B
    cudaFuncSetAttribute(attn_mma_kernel,
                         cudaFuncAttributeMaxDynamicSharedMemorySize, attn_smem);

    // 1) h = silu(x @ W1^T + b1), scattered to gate/q/k/v   (fp16 mma.sync)
    tc_gemm<0><<<dim3(2048 / 128, MROWS / 128), 256>>>(x, W1, b1, out);

    // 2) causal silu-attention -> g_o [b,s,d]  (fp16, paired-balanced)
    attn_mma_kernel<<<256, 256, attn_smem>>>();

    // 3) layernorm(o) * gate -> g_ng
    ln_gate_kernel<<<MROWS, 128>>>(lng, lnb);

    // 4) out = g_ng @ W2^T + b2                             (fp16 mma.sync)
    tc_gemm<1><<<dim3(512 / 128, MROWS / 128), 256>>>(nullptr, W2, b2, out);
}

// round 17
// speedup vs baseline: 2.8861x; 1.1003x over previous
#include <cuda_runtime.h>
#include <cuda_fp16.h>
#include <cstdint>

// Problem constants
#define BB 4
#define SS 2048
#define DD 512
#define HH 8
#define HD 64
#define MROWS (BB*SS)   // 8192

// Scratch (static device arrays -- allocation-free per harness rules)
__device__ float  g_gate[BB*SS*DD];      // [b,s,d] fp32
__device__ __half g_q[BB*HH*SS*HD];      // [b,h,s,d] fp16
__device__ __half g_k[BB*HH*SS*HD];
__device__ __half g_v[BB*HH*SS*HD];
__device__ float  g_o[BB*SS*DD];         // [b,s,d] fp32 (LN input)
__device__ __half g_xh[MROWS*DD];        // x in fp16
__device__ __half g_w1h[4*DD*DD];        // W1 in fp16
__device__ __half g_w2h[DD*DD];          // W2 in fp16
__device__ __half g_ngh[MROWS*DD];       // layernorm(o)*gate in fp16

// silu via tanh.approx: x*sigmoid(x) = h + h*tanh(h), h = x/2.  (1 MUFU)
__device__ __forceinline__ float silu_f(float x) {
    float h = 0.5f * x, th;
    asm("tanh.approx.f32 %0, %1;" : "=f"(th) : "f"(h));
    return fmaf(h, th, h);
}
__device__ __forceinline__ uint32_t f2h2(float lo, float hi) {
    uint32_t r;
    asm("cvt.rn.f16x2.f32 %0, %2, %1;" : "=r"(r) : "f"(lo), "f"(hi));
    return r;
}
__device__ __forceinline__ uint32_t smem_u32(const void* p) {
    uint32_t a;
    asm("{ .reg .u64 t; cvta.to.shared.u64 t, %1; cvt.u32.u64 %0, t; }"
        : "=r"(a) : "l"(p));
    return a;
}
__device__ __forceinline__ void cp16(uint32_t dst, const void* src) {
    asm volatile("cp.async.cg.shared.global [%0], [%1], 16;"
                 :: "r"(dst), "l"(src));
}
// D = A(16x16,row) * B(16x8,col) + D, fp16 in, f32 accum
__device__ __forceinline__ void mma_f16(float* c, const uint32_t* a, const uint32_t* b) {
    asm volatile(
        "mma.sync.aligned.m16n8k16.row.col.f32.f16.f16.f32 "
        "{%0,%1,%2,%3}, {%4,%5,%6,%7}, {%8,%9}, {%0,%1,%2,%3};"
        : "+f"(c[0]), "+f"(c[1]), "+f"(c[2]), "+f"(c[3])
        : "r"(a[0]), "r"(a[1]), "r"(a[2]), "r"(a[3]), "r"(b[0]), "r"(b[1]));
}
__device__ __forceinline__ void ldsm_x4(uint32_t* r, uint32_t addr) {
    asm volatile("ldmatrix.sync.aligned.m8n8.x4.shared.b16 {%0,%1,%2,%3}, [%4];"
                 : "=r"(r[0]), "=r"(r[1]), "=r"(r[2]), "=r"(r[3]) : "r"(addr));
}
__device__ __forceinline__ void ldsm_x2(uint32_t* r, uint32_t addr) {
    asm volatile("ldmatrix.sync.aligned.m8n8.x2.shared.b16 {%0,%1}, [%2];"
                 : "=r"(r[0]), "=r"(r[1]) : "r"(addr));
}
__device__ __forceinline__ void ldsm_x2t(uint32_t* r, uint32_t addr) {
    asm volatile("ldmatrix.sync.aligned.m8n8.x2.trans.shared.b16 {%0,%1}, [%2];"
                 : "=r"(r[0]), "=r"(r[1]) : "r"(addr));
}

// ---------------------------------------------------------------------------
// One-shot fp32 -> fp16 conversion of x, W1, W2 (float4 -> 2x half2)
// ---------------------------------------------------------------------------
#define NX4  (MROWS*DD/4)        // 1048576
#define NW14 (4*DD*DD/4)         // 262144
#define NW24 (DD*DD/4)           // 65536
#define NCVT (NX4+NW14+NW24)     // 1376256
__global__ void __launch_bounds__(256) cvt_kernel(
    const float* __restrict__ x, const float* __restrict__ W1,
    const float* __restrict__ W2)
{
    const int i = blockIdx.x * 256 + threadIdx.x;
    if (i >= NCVT) return;
    const float* src; __half* dst; int j;
    if (i < NX4)              { src = x;  dst = g_xh;  j = i; }
    else if (i < NX4 + NW14)  { src = W1; dst = g_w1h; j = i - NX4; }
    else                      { src = W2; dst = g_w2h; j = i - NX4 - NW14; }
    float4 v = ((const float4*)src)[j];
    ((uint2*)dst)[j] = make_uint2(f2h2(v.x, v.y), f2h2(v.z, v.w));
}

// ---------------------------------------------------------------------------
// fp16 cp.async-pipelined GEMM: C[M,N] = A[M,512] @ W[N,512]^T (+bias,+epi)
// CTA: 128x128 tile, 256 threads = 8 warps (2 M x 4 N), warp = 64x32.
// 3-stage cp.async pipeline over 32-k blocks: per iter wait_group + one
// __syncthreads + 4x cp.async(16B) issue + 2 k16 MMA steps. No register
// staging, no cvt in the loop. Smem stride 40 halves -> conflict-free LDSM.
// MODE 0: A = g_xh,  W = g_w1h, epi = silu + scatter gate(f32)/q,k,v(f16)
// MODE 1: A = g_ngh, W = g_w2h, epi = +b2 -> out(f32)
// ---------------------------------------------------------------------------
#define KH 40
#define MATB (128*KH*2)          // bytes per matrix per stage (10240)
#define STAGEB (2*MATB)          // bytes per stage (A+B) (20480)

__device__ __forceinline__ void gemm_issue(
    int kb, int tid, int row0, int col0, uint32_t smbase,
    const __half* __restrict__ Ah, const __half* __restrict__ Wh)
{
    const uint32_t sb = smbase + (kb % 3) * STAGEB;
    #pragma unroll
    for (int l = 0; l < 2; l++) {
        const int idx = tid + l * 256;        // 0..511
        const int r   = idx >> 2;             // row 0..127
        const int c   = idx & 3;              // 16B chunk 0..3
        cp16(sb + (r * KH + c * 8) * 2,
             Ah + (size_t)(row0 + r) * 512 + kb * 32 + c * 8);
        cp16(sb + MATB + (r * KH + c * 8) * 2,
             Wh + (size_t)(col0 + r) * 512 + kb * 32 + c * 8);
    }
    asm volatile("cp.async.commit_group;" ::: "memory");
}

template<int MODE>
__global__ void __launch_bounds__(256) tc_gemm(
    const float* __restrict__ bias, float* __restrict__ out)
{
    extern __shared__ __half gsh[];
    const __half* Ah = (MODE == 0) ? g_xh  : g_ngh;
    const __half* Wh = (MODE == 0) ? g_w1h : g_w2h;

    const int tid  = threadIdx.x;
    const int wid  = tid >> 5;
    const int lane = tid & 31;
    const int g    = lane >> 2;
    const int t    = lane & 3;
    const int row0 = blockIdx.y * 128;
    const int col0 = blockIdx.x * 128;
    const int wm   = (wid >> 2) * 64;
    const int wn   = (wid & 3) * 32;

    const uint32_t smbase = smem_u32(gsh);
    const uint32_t aOff = (((wm + (lane & 15)) * KH) + ((lane >> 4) << 3)) * 2;
    const uint32_t bOff = MATB +
        (((wn + (lane & 7)) * KH) + (((lane >> 3) & 1) << 3)) * 2;

    float acc[4][4][4];
    #pragma unroll
    for (int i = 0; i < 4; i++)
        #pragma unroll
        for (int j = 0; j < 4; j++)
            #pragma unroll
            for (int q = 0; q < 4; q++) acc[i][j][q] = 0.0f;

    gemm_issue(0, tid, row0, col0, smbase, Ah, Wh);
    gemm_issue(1, tid, row0, col0, smbase, Ah, Wh);

    for (int kb = 0; kb < 16; kb++) {
        if (kb < 14) asm volatile("cp.async.wait_group 1;" ::: "memory");
        else         asm volatile("cp.async.wait_group 0;" ::: "memory");
        __syncthreads();
        if (kb < 14) gemm_issue(kb + 2, tid, row0, col0, smbase, Ah, Wh);

        const uint32_t sb = smbase + (kb % 3) * STAGEB;
        #pragma unroll
        for (int k16 = 0; k16 < 2; k16++) {
            uint32_t af[4][4];
            #pragma unroll
            for (int mt = 0; mt < 4; mt++)
                ldsm_x4(af[mt], sb + aOff + mt * (16 * KH * 2) + k16 * 32);
            uint32_t bf[4][2];
            #pragma unroll
            for (int nt = 0; nt < 4; nt++)
                ldsm_x2(bf[nt], sb + bOff + nt * (8 * KH * 2) + k16 * 32);
            #pragma unroll
            for (int mt = 0; mt < 4; mt++)
                #pragma unroll
                for (int nt = 0; nt < 4; nt++)
                    mma_f16(acc[mt][nt], af[mt], bf[nt]);
        }
    }

    #pragma unroll
    for (int mt = 0; mt < 4; mt++) {
        #pragma unroll
        for (int half = 0; half < 2; half++) {
            const int r = row0 + wm + mt * 16 + g + half * 8;
            const int b = r >> 11;
            const int s = r & 2047;
            #pragma unroll
            for (int nt = 0; nt < 4; nt++) {
                const int j = col0 + wn + nt * 8 + 2 * t;
                float2 v;
                v.x = acc[mt][nt][half * 2 + 0] + __ldg(&bias[j]);
                v.y = acc[mt][nt][half * 2 + 1] + __ldg(&bias[j + 1]);
                if (MODE == 0) {
                    v.x = silu_f(v.x);
                    v.y = silu_f(v.y);
                    const int c   = j >> 9;
                    const int rem = j & 511;
                    if (c == 0) {
                        *(float2*)&g_gate[(size_t)r * 512 + rem] = v;   // fp32
                    } else {
                        const int head = rem >> 6;
                        const int d    = rem & 63;
                        __half* dst = (c == 1) ? g_q : ((c == 2) ? g_k : g_v);
                        *(uint32_t*)&dst[((size_t)(b * 8 + head) * 2048 + s) * 64 + d] =
                            f2h2(v.x, v.y);                             // fp16
                    }
                } else {
                    *(float2*)&out[(size_t)r * 512 + j] = v;
                }
            }
        }
    }
}

// ---------------------------------------------------------------------------
// Causal HSTU attention, fp16 mma.sync, balanced pair scheduling (R16 body,
// silu via tanh.approx). Grid = 256 CTAs; CTA (bh,pa) does query tiles
// 15-pa then pa (34 key-tiles each, exactly constant).
// ---------------------------------------------------------------------------
#define ASTH 72

__global__ void __launch_bounds__(256) attn_mma_kernel() {
    extern __shared__ __half smh[];
    __half* Qs = smh;                    // [128][ASTH] fp16 [query][dim]
    __half* Ks = smh + 128 * ASTH;       // [64][ASTH]  fp16 [key][dim]
    __half* Vs = Ks + 64 * ASTH;         // [64][ASTH]  fp16 [key][dim] (natural)
    __half* St = Vs + 64 * ASTH;         // [128][ASTH] fp16 [query][key]

    const int tid  = threadIdx.x;
    const int wid  = tid >> 5;
    const int lane = tid & 31;
    const int g    = lane >> 2;
    const int t    = lane & 3;
    const int cta  = blockIdx.x;         // 0..255
    const int bh   = cta >> 3;           // 0..31
    const int pa   = cta & 7;            // 0..7
    const int b    = bh >> 3;
    const int h    = bh & 7;
    const size_t base = (size_t)bh * SS * HD;
    const __half* qp = g_q + base;
    const __half* kp = g_k + base;
    const __half* vp = g_v + base;
    const int wm = (wid >> 1) * 32;      // query offset: 0,32,64,96
    const int wn = (wid & 1) * 32;       // key/dim offset: 0,32

    const uint32_t qAddr0 = smem_u32(Qs) +
        (((wm + (lane & 15)) * ASTH) + ((lane >> 4) << 3)) * 2;
    const uint32_t kAddr0 = smem_u32(Ks) +
        (((wn + (lane & 7)) * ASTH) + (((lane >> 3) & 1) << 3)) * 2;
    const uint32_t sAddr0 = smem_u32(St) +
        (((wm + (lane & 15)) * ASTH) + ((lane >> 4) << 3)) * 2;
    const uint32_t vAddr0 = smem_u32(Vs) + (((lane & 15) * ASTH) + wn) * 2;

    #pragma unroll 1
    for (int sub = 0; sub < 2; sub++) {
        const int qt = sub ? pa : (15 - pa);   // heavy tile first
        const int s0 = qt * 128;
        const int last = 2 * qt + 1;

        __syncthreads();   // protect Qs/St/Ks/Vs from previous sub-tile reads

        // Stage Q (128 x 64 fp16): raw uint4 copies
        #pragma unroll
        for (int l = 0; l < 4; l++) {
            const int idx = tid + l * 256;
            const int r   = idx >> 3;
            const int c8  = (idx & 7) << 3;
            *(uint4*)&Qs[r * ASTH + c8] =
                *(const uint4*)&qp[(size_t)(s0 + r) * 64 + c8];
        }

        float oacc[2][4][4];
        #pragma unroll
        for (int m = 0; m < 2; m++)
            #pragma unroll
            for (int i = 0; i < 4; i++)
                #pragma unroll
                for (int j = 0; j < 4; j++) oacc[m][i][j] = 0.0f;

        // prefetch K/V tile 0 (raw fp16)
        uint4 pk[2], pv[2];
        #pragma unroll
        for (int l = 0; l < 2; l++) {
            const int idx = tid + l * 256;
            const int r   = idx >> 3;
            const int c8  = (idx & 7) << 3;
            pk[l] = *(const uint4*)&kp[(size_t)r * 64 + c8];
            pv[l] = *(const uint4*)&vp[(size_t)r * 64 + c8];
        }

        for (int kt = 0; kt <= last; kt++) {
            const int t0 = kt * 64;
            __syncthreads();   // prev-iter Ks/Vs/St reads done (and Qs staged)

            #pragma unroll
            for (int l = 0; l < 2; l++) {
                const int idx = tid + l * 256;
                const int r   = idx >> 3;
                const int c8  = (idx & 7) << 3;
                *(uint4*)&Ks[r * ASTH + c8] = pk[l];
                *(uint4*)&Vs[r * ASTH + c8] = pv[l];
            }
            __syncthreads();

            // prefetch next K/V tile; latency hides under the MMA loops
            if (kt < last) {
                const int tn = (kt + 1) * 64;
                #pragma unroll
                for (int l = 0; l < 2; l++) {
                    const int idx = tid + l * 256;
                    const int r   = idx >> 3;
                    const int c8  = (idx & 7) << 3;
                    pk[l] = *(const uint4*)&kp[(size_t)(tn + r) * 64 + c8];
                    pv[l] = *(const uint4*)&vp[(size_t)(tn + r) * 64 + c8];
                }
            }

            // ---- GEMM 1: scores = Q @ K^T (per warp: M=32, N=32; k=dim)
            float sacc[2][4][4];
            #pragma unroll
            for (int m = 0; m < 2; m++)
                #pragma unroll
                for (int i = 0; i < 4; i++)
                    #pragma unroll
                    for (int j = 0; j < 4; j++) sacc[m][i][j] = 0.0f;

            #pragma unroll
            for (int k16 = 0; k16 < 4; k16++) {
                uint32_t af[2][4];
                #pragma unroll
                for (int mt = 0; mt < 2; mt++)
                    ldsm_x4(af[mt], qAddr0 + mt * (16 * ASTH * 2) + k16 * 32);
                uint32_t bf[4][2];
                #pragma unroll
                for (int nt = 0; nt < 4; nt++)
                    ldsm_x2(bf[nt], kAddr0 + nt * (8 * ASTH * 2) + k16 * 32);
                #pragma unroll
                for (int mt = 0; mt < 2; mt++)
                    #pragma unroll
                    for (int nt = 0; nt < 4; nt++)
                        mma_f16(sacc[mt][nt], af[mt], bf[nt]);
            }

            // silu + causal mask on fragments, round to fp16 into St
            const bool diag = (kt >= 2 * qt);
            #pragma unroll
            for (int mt = 0; mt < 2; mt++) {
                #pragma unroll
                for (int nt = 0; nt < 4; nt++) {
                    const int klocal = wn + nt * 8 + 2 * t;
                    const int key    = t0 + klocal;
                    #pragma unroll
                    for (int half = 0; half < 2; half++) {
                        const int qlocal = wm + mt * 16 + g + half * 8;
                        const int qrow   = s0 + qlocal;
                        float v0 = silu_f(sacc[mt][nt][half * 2 + 0] * 0.125f);
                        float v1 = silu_f(sacc[mt][nt][half * 2 + 1] * 0.125f);
                        if (diag) {
                            if (key     > qrow) v0 = 0.0f;
                            if (key + 1 > qrow) v1 = 0.0f;
                        }
                        *(uint32_t*)&St[qlocal * ASTH + klocal] = f2h2(v0, v1);
                    }
                }
            }
            __syncthreads();

            // ---- GEMM 2: O += St @ V  (A=St [q][key]; B=Vs [key][dim] via
            //      ldmatrix.trans; k=key)
            #pragma unroll
            for (int k16 = 0; k16 < 4; k16++) {
                uint32_t af[2][4];
                #pragma unroll
                for (int mt = 0; mt < 2; mt++)
                    ldsm_x4(af[mt], sAddr0 + mt * (16 * ASTH * 2) + k16 * 32);
                uint32_t bf[4][2];
                #pragma unroll
                for (int nt = 0; nt < 4; nt++)
                    ldsm_x2t(bf[nt], vAddr0 + k16 * (16 * ASTH * 2) + nt * 16);
                #pragma unroll
                for (int mt = 0; mt < 2; mt++)
                    #pragma unroll
                    for (int nt = 0; nt < 4; nt++)
                        mma_f16(oacc[mt][nt], af[mt], bf[nt]);
            }
        }

        // Write O in [b, s, h*64+dim] layout (fp32)
        #pragma unroll
        for (int mt = 0; mt < 2; mt++) {
            #pragma unroll
            for (int nt = 0; nt < 4; nt++) {
                const int dim = wn + nt * 8 + 2 * t;
                #pragma unroll
                for (int half = 0; half < 2; half++) {
                    const int srow = s0 + wm + mt * 16 + g + half * 8;
                    float2 ov = make_float2(oacc[mt][nt][half * 2 + 0],
                                            oacc[mt][nt][half * 2 + 1]);
                    *(float2*)&g_o[((size_t)(b * SS + srow)) * DD + h * 64 + dim] = ov;
                }
            }
        }
    }
}

// ---------------------------------------------------------------------------
// LayerNorm(o) * gate  -> g_ngh (fp16 for GEMM2)
// ---------------------------------------------------------------------------
__global__ void __launch_bounds__(128) ln_gate_kernel(
    const float* __restrict__ lng, const float* __restrict__ lnb)
{
    const int row = blockIdx.x;
    const int tid = threadIdx.x;
    const float* op = g_o + (size_t)row * DD;

    float4 x = *(const float4*)&op[tid * 4];
    float s = x.x + x.y + x.z + x.w;

    const int lane = tid & 31, wid = tid >> 5;
    __shared__ float r1[4], r2[4];

    #pragma unroll
    for (int off = 16; off; off >>= 1) s += __shfl_xor_sync(0xffffffffu, s, off);
    if (lane == 0) r1[wid] = s;
    __syncthreads();
    const float m = (r1[0] + r1[1] + r1[2] + r1[3]) * (1.0f / 512.0f);

    const float dx = x.x - m, dy = x.y - m, dz = x.z - m, dw = x.w - m;
    float sq = dx * dx + dy * dy + dz * dz + dw * dw;
    #pragma unroll
    for (int off = 16; off; off >>= 1) sq += __shfl_xor_sync(0xffffffffu, sq, off);
    if (lane == 0) r2[wid] = sq;
    __syncthreads();
    const float var = (r2[0] + r2[1] + r2[2] + r2[3]) * (1.0f / 512.0f);
    const float inv = rsqrtf(var + 1e-5f);

    float4 gv = *(const float4*)&lng[tid * 4];
    float4 bv = *(const float4*)&lnb[tid * 4];
    float4 gg = *(const float4*)&g_gate[(size_t)row * DD + tid * 4];
    float4 o;
    o.x = (dx * inv * gv.x + bv.x) * gg.x;
    o.y = (dy * inv * gv.y + bv.y) * gg.y;
    o.z = (dz * inv * gv.z + bv.z) * gg.z;
    o.w = (dw * inv * gv.w + bv.w) * gg.w;
    *(uint2*)&g_ngh[(size_t)row * DD + tid * 4] =
        make_uint2(f2h2(o.x, o.y), f2h2(o.z, o.w));
}

// ---------------------------------------------------------------------------
extern "C" void kernel_launch(void* const* d_in, const int* in_sizes, int n_in,
                              void* d_out, int out_size) {
    const float* x   = (const float*)d_in[0];
    const float* W1  = (const float*)d_in[1];
    const float* b1  = (const float*)d_in[2];
    const float* lng = (const float*)d_in[3];
    const float* lnb = (const float*)d_in[4];
    const float* W2  = (const float*)d_in[5];
    const float* b2  = (const float*)d_in[6];
    float* out = (float*)d_out;

    const int gemm_smem = 3 * STAGEB;                          // 61440 B
    cudaFuncSetAttribute(tc_gemm<0>, cudaFuncAttributeMaxDynamicSharedMemorySize,
                         gemm_smem);
    cudaFuncSetAttribute(tc_gemm<1>, cudaFuncAttributeMaxDynamicSharedMemorySize,
                         gemm_smem);
    const int attn_smem = 384 * ASTH * (int)sizeof(__half);    // 55296 B
    cudaFuncSetAttribute(attn_mma_kernel,
                         cudaFuncAttributeMaxDynamicSharedMemorySize, attn_smem);

    // 0) convert x, W1, W2 to fp16 once
    cvt_kernel<<<(NCVT + 255) / 256, 256>>>(x, W1, W2);

    // 1) h = silu(x @ W1^T + b1), scattered to gate/q/k/v   (fp16 cp.async)
    tc_gemm<0><<<dim3(2048 / 128, MROWS / 128), 256, gemm_smem>>>(b1, out);

    // 2) causal silu-attention -> g_o [b,s,d]  (fp16, paired-balanced)
    attn_mma_kernel<<<256, 256, attn_smem>>>();

    // 3) layernorm(o) * gate -> g_ngh (fp16)
    ln_gate_kernel<<<MROWS, 128>>>(lng, lnb);

    // 4) out = g_ngh @ W2^T + b2                            (fp16 cp.async)
    tc_gemm<1><<<dim3(512 / 128, MROWS / 128), 256, gemm_smem>>>(b2, out);
}